// round 7
// baseline (speedup 1.0000x reference)
#include <cuda_runtime.h>
#include <cuda_fp16.h>
#include <cstdint>

#define B 2
#define C 192
#define C3 576
#define SDIM 32
#define NPTS 32768           // 32^3
#define HEADS 4
#define CH 48
#define EPS 1e-12f

// ---------------- scratch (static device allocations) ----------------
__device__ __half g_qkvh[(size_t)B * C3 * NPTS];     // after 1x1 conv (fp16)
__device__ __half g_dwh [(size_t)B * C3 * NPTS];     // after dwconv: q,k,v fp16
__device__ float  g_ssq[B * 2 * C];                  // sum of squares of ROUNDED q/k
__device__ float  g_at [B * HEADS * CH * CH];        // attention logits / probs
__device__ __half g_wh [C3 * C];                     // qkv weights fp16
__device__ __half g_w2h[B * C * C];                  // fused proj∘attn weights fp16

// ================= mma.sync helpers =================
__device__ __forceinline__ uint32_t smem_u32(const void* p) {
    uint32_t a;
    asm("{ .reg .u64 t; cvta.to.shared.u64 t, %1; cvt.u32.u64 %0, t; }" : "=r"(a) : "l"(p));
    return a;
}
__device__ __forceinline__ void ldsm4(uint32_t* r, uint32_t a) {
    asm volatile("ldmatrix.sync.aligned.m8n8.x4.shared.b16 {%0,%1,%2,%3}, [%4];"
                 : "=r"(r[0]), "=r"(r[1]), "=r"(r[2]), "=r"(r[3]) : "r"(a));
}
__device__ __forceinline__ void ldsm2(uint32_t* r, uint32_t a) {
    asm volatile("ldmatrix.sync.aligned.m8n8.x2.shared.b16 {%0,%1}, [%2];"
                 : "=r"(r[0]), "=r"(r[1]) : "r"(a));
}
__device__ __forceinline__ void ldsm2t(uint32_t* r, uint32_t a) {
    asm volatile("ldmatrix.sync.aligned.m8n8.x2.trans.shared.b16 {%0,%1}, [%2];"
                 : "=r"(r[0]), "=r"(r[1]) : "r"(a));
}
__device__ __forceinline__ void mma_f16(float* d, const uint32_t* a, const uint32_t* b) {
    asm volatile(
        "mma.sync.aligned.m16n8k16.row.col.f32.f16.f16.f32 "
        "{%0,%1,%2,%3}, {%4,%5,%6,%7}, {%8,%9}, {%0,%1,%2,%3};"
        : "+f"(d[0]), "+f"(d[1]), "+f"(d[2]), "+f"(d[3])
        : "r"(a[0]), "r"(a[1]), "r"(a[2]), "r"(a[3]), "r"(b[0]), "r"(b[1]));
}
__device__ __forceinline__ uint2 cvt4h(const float4 v) {
    __half2 h0 = __floats2half2_rn(v.x, v.y);
    __half2 h1 = __floats2half2_rn(v.z, v.w);
    uint2 r;
    r.x = *reinterpret_cast<uint32_t*>(&h0);
    r.y = *reinterpret_cast<uint32_t*>(&h1);
    return r;
}
#define CP_ASYNC16(dst, src) \
    asm volatile("cp.async.ca.shared.global [%0], [%1], 16;" :: "r"(dst), "l"(src))
#define CP_COMMIT() asm volatile("cp.async.commit_group;")

// ---------------- qkv weight fp16 conversion + attn buffer zeroing ----------------
__global__ void cvtW(const float* __restrict__ qkv_w, __half* __restrict__ wh,
                     float* __restrict__ attn)
{
    int i = blockIdx.x * 256 + threadIdx.x;
    const int T0 = C3 * C;
    const int T1 = T0 + B * HEADS * CH * CH;
    if (i < T0)       wh[i] = __float2half_rn(qkv_w[i]);
    else if (i < T1)  attn[i - T0] = 0.f;
}

// ---------------- 1x1 conv GEMM via fp16 mma.sync ----------------
// grid: (O/BM, NPTS/BN, B) — o-tile on x so concurrent blocks share the X slab in L2
#define BMg 192
#define BNg 128
#define BKg 32
#define PA 40
#define PB 136

template<int XHALF, int OHALF>
__global__ __launch_bounds__(512) void gemm_mma(
    const void* __restrict__ Xall, size_t xbs,
    const __half* __restrict__ WH, size_t wbs,
    const float* __restrict__ bias, void* __restrict__ Yall, size_t ybs)
{
    __shared__ __align__(16) uint16_t sA[BMg * PA];
    __shared__ __align__(16) uint16_t sB[BKg * PB];

    const int tid = threadIdx.x, wid = tid >> 5, lane = tid & 31;
    const int o0 = blockIdx.x * BMg;
    const int n0 = blockIdx.y * BNg;
    const __half* W = WH + (size_t)blockIdx.z * wbs;

    const int warp_m = (wid >> 2) * 48;
    const int warp_n = (wid & 3) * 32;

    const uint32_t bA = smem_u32(sA);
    const uint32_t bB = smem_u32(sB);
    const uint32_t aOff = ((warp_m + (lane & 15)) * PA + (lane >> 4) * 8) * 2;
    const uint32_t bOff = ((lane & 15) * PB + warp_n) * 2;

    float acc[3][4][4] = {};

    for (int kc = 0; kc < C; kc += BKg) {
        #pragma unroll
        for (int q = 0; q < 3; q++) {
            int t = tid + q * 512;
            int m = t >> 3, k4 = (t & 7) * 4;
            *reinterpret_cast<uint2*>(&sA[m * PA + k4]) =
                *reinterpret_cast<const uint2*>(&W[(size_t)(o0 + m) * C + kc + k4]);
        }
        if (XHALF) {
            const __half* X = (const __half*)Xall + (size_t)blockIdx.z * xbs;
            #pragma unroll
            for (int q = 0; q < 2; q++) {
                int t = tid + q * 512;
                int c = t >> 5, n4 = (t & 31) * 4;
                *reinterpret_cast<uint2*>(&sB[c * PB + n4]) = *reinterpret_cast<const uint2*>(
                    &X[(size_t)(kc + c) * NPTS + n0 + n4]);
            }
        } else {
            const float* X = (const float*)Xall + (size_t)blockIdx.z * xbs;
            #pragma unroll
            for (int q = 0; q < 2; q++) {
                int t = tid + q * 512;
                int c = t >> 5, n4 = (t & 31) * 4;
                float4 xv = *reinterpret_cast<const float4*>(&X[(size_t)(kc + c) * NPTS + n0 + n4]);
                *reinterpret_cast<uint2*>(&sB[c * PB + n4]) = cvt4h(xv);
            }
        }
        __syncthreads();

        #pragma unroll
        for (int ks = 0; ks < 2; ks++) {
            uint32_t Bf[4][2];
            #pragma unroll
            for (int j = 0; j < 4; j++)
                ldsm2t(Bf[j], bB + bOff + j * 16 + ks * (16 * PB * 2));
            #pragma unroll
            for (int i = 0; i < 3; i++) {
                uint32_t Af[4];
                ldsm4(Af, bA + aOff + i * (16 * PA * 2) + ks * 32);
                #pragma unroll
                for (int j = 0; j < 4; j++)
                    mma_f16(acc[i][j], Af, Bf[j]);
            }
        }
        __syncthreads();
    }

    #pragma unroll
    for (int i = 0; i < 3; i++) {
        int m = o0 + warp_m + i * 16 + (lane >> 2);
        float bv0 = bias[m], bv1 = bias[m + 8];
        #pragma unroll
        for (int j = 0; j < 4; j++) {
            int n = n0 + warp_n + j * 8 + (lane & 3) * 2;
            if (OHALF) {
                __half* Y = (__half*)Yall + (size_t)blockIdx.z * ybs;
                __half2 r0 = __floats2half2_rn(acc[i][j][0] + bv0, acc[i][j][1] + bv0);
                __half2 r1 = __floats2half2_rn(acc[i][j][2] + bv1, acc[i][j][3] + bv1);
                *reinterpret_cast<__half2*>(&Y[(size_t)m * NPTS + n]) = r0;
                *reinterpret_cast<__half2*>(&Y[(size_t)(m + 8) * NPTS + n]) = r1;
            } else {
                float* Y = (float*)Yall + (size_t)blockIdx.z * ybs;
                float2 r0 = {acc[i][j][0] + bv0, acc[i][j][1] + bv0};
                float2 r1 = {acc[i][j][2] + bv1, acc[i][j][3] + bv1};
                *reinterpret_cast<float2*>(&Y[(size_t)m * NPTS + n]) = r0;
                *reinterpret_cast<float2*>(&Y[(size_t)(m + 8) * NPTS + n]) = r1;
            }
        }
    }
}

// ---------------- depthwise 3x3x3 (fp16 in) -> fp16 q,k,v + ssq of rounded q/k ----------------
__global__ __launch_bounds__(256) void dwconv3(
    const __half* __restrict__ in, const float* __restrict__ w,
    const float* __restrict__ bias, __half* __restrict__ outh,
    float* __restrict__ ssq)
{
    int bc = blockIdx.x;
    int b  = bc / C3;
    int c  = bc % C3;
    const __half* vol = in + (size_t)bc * NPTS;
    __half* op = outh + (size_t)bc * NPTS;

    float wr[27];
    #pragma unroll
    for (int i = 0; i < 27; i++) wr[i] = w[c * 27 + i];
    float bv = bias[c];

    __shared__ float P[3][34][36];
    __shared__ float sred[8];
    int tid = threadIdx.x;
    for (int i = tid; i < 3 * 34 * 36; i += 256) ((float*)P)[i] = 0.f;
    __syncthreads();
    {
        int y = tid >> 3, x4 = (tid & 7) * 4;
        uint2 raw = *reinterpret_cast<const uint2*>(&vol[y * 32 + x4]);
        __half2 hA = *reinterpret_cast<__half2*>(&raw.x);
        __half2 hB = *reinterpret_cast<__half2*>(&raw.y);
        P[0][1 + y][1 + x4 + 0] = __half2float(hA.x);
        P[0][1 + y][1 + x4 + 1] = __half2float(hA.y);
        P[0][1 + y][1 + x4 + 2] = __half2float(hB.x);
        P[0][1 + y][1 + x4 + 3] = __half2float(hB.y);
    }
    __syncthreads();

    int tx4 = (tid & 7) * 4;
    int ty  = tid >> 3;
    float qs = 0.f;
    const bool is_qk = (c < 2 * C);

    for (int z = 0; z < SDIM; z++) {
        int nb = (z + 1) % 3;
        if (z + 1 < SDIM) {
            int y = tid >> 3, x4 = (tid & 7) * 4;
            uint2 raw = *reinterpret_cast<const uint2*>(&vol[(size_t)(z + 1) * 1024 + y * 32 + x4]);
            __half2 hA = *reinterpret_cast<__half2*>(&raw.x);
            __half2 hB = *reinterpret_cast<__half2*>(&raw.y);
            P[nb][1 + y][1 + x4 + 0] = __half2float(hA.x);
            P[nb][1 + y][1 + x4 + 1] = __half2float(hA.y);
            P[nb][1 + y][1 + x4 + 2] = __half2float(hB.x);
            P[nb][1 + y][1 + x4 + 3] = __half2float(hB.y);
        } else {
            for (int i = tid; i < 34 * 36; i += 256) ((float*)P[nb])[i] = 0.f;
        }
        __syncthreads();
        int pm = (z + 2) % 3;
        int pc = z % 3;
        float a0 = bv, a1 = bv, a2 = bv, a3 = bv;
        #pragma unroll
        for (int dz = 0; dz < 3; dz++) {
            int pi = (dz == 0) ? pm : (dz == 1) ? pc : nb;
            #pragma unroll
            for (int dy = 0; dy < 3; dy++) {
                const float* row = &P[pi][ty + dy][tx4];
                float4 rA = *reinterpret_cast<const float4*>(row);
                float2 rB = *reinterpret_cast<const float2*>(row + 4);
                float w0 = wr[dz * 9 + dy * 3 + 0];
                float w1 = wr[dz * 9 + dy * 3 + 1];
                float w2 = wr[dz * 9 + dy * 3 + 2];
                a0 += w0 * rA.x + w1 * rA.y + w2 * rA.z;
                a1 += w0 * rA.y + w1 * rA.z + w2 * rA.w;
                a2 += w0 * rA.z + w1 * rA.w + w2 * rB.x;
                a3 += w0 * rA.w + w1 * rB.x + w2 * rB.y;
            }
        }
        size_t off = (size_t)z * 1024 + ty * 32 + tx4;
        __half2 h0 = __floats2half2_rn(a0, a1);
        __half2 h1 = __floats2half2_rn(a2, a3);
        uint2 hv = {*reinterpret_cast<uint32_t*>(&h0), *reinterpret_cast<uint32_t*>(&h1)};
        *reinterpret_cast<uint2*>(&op[off]) = hv;
        if (is_qk) {
            // ssq of the ROUNDED values so the norm matches the fp16 numerator
            float r0 = __half2float(h0.x), r1 = __half2float(h0.y);
            float r2 = __half2float(h1.x), r3 = __half2float(h1.y);
            qs += r0 * r0 + r1 * r1 + r2 * r2 + r3 * r3;
        }
        __syncthreads();
    }

    if (is_qk) {
        #pragma unroll
        for (int o = 16; o > 0; o >>= 1) qs += __shfl_xor_sync(~0u, qs, o);
        if ((tid & 31) == 0) sred[tid >> 5] = qs;
        __syncthreads();
        if (tid < 8) {
            float v = sred[tid];
            #pragma unroll
            for (int o = 4; o > 0; o >>= 1) v += __shfl_xor_sync(0xffu, v, o);
            if (tid == 0) ssq[b * 2 * C + c] = v;
        }
    }
}

// ---------------- q @ k^T via fp16 mma.sync ----------------
#define QKC 128                      // k-chunk per stage
#define QKP 136                      // smem pitch in halfs
#define QK_ARR (48 * QKP * 2)        // bytes per array (13056)
#define QK_STAGE (2 * QK_ARR)        // Q, K
#define QK_NSPL 16
#define QK_SLAB (NPTS / QK_NSPL)     // 2048
#define QK_SMEM (2 * QK_STAGE + 48 * 49 * 4)

__global__ __launch_bounds__(256) void qk_mma(
    const __half* __restrict__ dwh, float* __restrict__ attn)
{
    extern __shared__ char smem[];
    float* sAcc = reinterpret_cast<float*>(smem + 2 * QK_STAGE);
    const int tid = threadIdx.x, wid = tid >> 5, lane = tid & 31;
    const int b = blockIdx.z, h = blockIdx.y;
    const int n0 = blockIdx.x * QK_SLAB;

    const __half* srcs[2] = {
        dwh + ((size_t)b * C3 + h * CH) * NPTS,        // Q
        dwh + ((size_t)b * C3 + C + h * CH) * NPTS     // K
    };
    const uint32_t sbase = smem_u32(smem);

    for (int i = tid; i < 48 * 49; i += 256) sAcc[i] = 0.f;

    // per-thread load slots: 6 x 16B per stage
    int la[6], lr[6], lc[6];
    #pragma unroll
    for (int q = 0; q < 6; q++) {
        int idx = tid + q * 256;         // 0..1535
        la[q] = idx / 768;               // array (Q or K)
        int rem = idx % 768;
        lr[q] = rem / 16;                // row 0..47
        lc[q] = (rem % 16) * 8;          // col in halfs
    }

    const int NCH = QK_SLAB / QKC;       // 16
    #pragma unroll
    for (int q = 0; q < 6; q++) {
        uint32_t dst = sbase + la[q] * QK_ARR + (lr[q] * QKP + lc[q]) * 2;
        CP_ASYNC16(dst, srcs[la[q]] + (size_t)lr[q] * NPTS + n0 + lc[q]);
    }
    CP_COMMIT();

    float acc[3][6][4] = {};
    const int k0 = wid * 16;

    for (int ch = 0; ch < NCH; ch++) {
        if (ch + 1 < NCH) {
            uint32_t st = ((ch + 1) & 1) * QK_STAGE;
            int nb = n0 + (ch + 1) * QKC;
            #pragma unroll
            for (int q = 0; q < 6; q++) {
                uint32_t dst = sbase + st + la[q] * QK_ARR + (lr[q] * QKP + lc[q]) * 2;
                CP_ASYNC16(dst, srcs[la[q]] + (size_t)lr[q] * NPTS + nb + lc[q]);
            }
            CP_COMMIT();
            asm volatile("cp.async.wait_group 1;");
        } else {
            asm volatile("cp.async.wait_group 0;");
        }
        __syncthreads();

        const uint32_t st = sbase + (ch & 1) * QK_STAGE;
        uint32_t Af[3][4], Bf[6][2];
        #pragma unroll
        for (int i = 0; i < 3; i++) {
            uint32_t off = ((i * 16 + (lane & 15)) * QKP + k0 + (lane >> 4) * 8) * 2;
            ldsm4(Af[i], st + off);
        }
        #pragma unroll
        for (int j = 0; j < 6; j++) {
            uint32_t off = ((j * 8 + (lane & 7)) * QKP + k0 + ((lane >> 3) & 1) * 8) * 2;
            ldsm2(Bf[j], st + QK_ARR + off);
        }
        #pragma unroll
        for (int i = 0; i < 3; i++)
            #pragma unroll
            for (int j = 0; j < 6; j++)
                mma_f16(acc[i][j], Af[i], Bf[j]);
        __syncthreads();
    }

    #pragma unroll
    for (int i = 0; i < 3; i++) {
        int m = i * 16 + (lane >> 2);
        #pragma unroll
        for (int j = 0; j < 6; j++) {
            int n = j * 8 + (lane & 3) * 2;
            atomicAdd(&sAcc[m * 49 + n],           acc[i][j][0]);
            atomicAdd(&sAcc[m * 49 + n + 1],       acc[i][j][1]);
            atomicAdd(&sAcc[(m + 8) * 49 + n],     acc[i][j][2]);
            atomicAdd(&sAcc[(m + 8) * 49 + n + 1], acc[i][j][3]);
        }
    }
    __syncthreads();
    float* dst = attn + (size_t)(b * HEADS + h) * CH * CH;
    for (int i = tid; i < CH * CH; i += 256)
        atomicAdd(&dst[i], sAcc[(i / CH) * 49 + (i % CH)]);
}

// ---------------- scale by 1/max(||.||,eps) + temperature, softmax over e ----------------
__global__ void softmaxk(float* __restrict__ attn, const float* __restrict__ ssq,
                         const float* __restrict__ temp)
{
    int gw = blockIdx.x * (blockDim.x / 32) + (threadIdx.x >> 5);
    if (gw >= B * HEADS * CH) return;
    int lane = threadIdx.x & 31;
    int c = gw % CH, bh = gw / CH, h = bh % HEADS, b = bh / HEADS;
    float* row = attn + (size_t)gw * CH;
    float iq = 1.f / fmaxf(sqrtf(ssq[b * 2 * C + h * CH + c]), EPS);
    float t  = temp[h];
    int e0 = lane, e1 = lane + 32;
    float ik0 = 1.f / fmaxf(sqrtf(ssq[b * 2 * C + C + h * CH + e0]), EPS);
    float x0 = row[e0] * iq * ik0 * t;
    float x1 = -1e30f;
    if (e1 < CH) {
        float ik1 = 1.f / fmaxf(sqrtf(ssq[b * 2 * C + C + h * CH + e1]), EPS);
        x1 = row[e1] * iq * ik1 * t;
    }
    float m = fmaxf(x0, x1);
    #pragma unroll
    for (int o = 16; o > 0; o >>= 1) m = fmaxf(m, __shfl_xor_sync(~0u, m, o));
    float ex0 = expf(x0 - m);
    float ex1 = (e1 < CH) ? expf(x1 - m) : 0.f;
    float s = ex0 + ex1;
    #pragma unroll
    for (int o = 16; o > 0; o >>= 1) s += __shfl_xor_sync(~0u, s, o);
    float r = 1.f / s;
    row[e0] = ex0 * r;
    if (e1 < CH) row[e1] = ex1 * r;
}

// ---------------- fuse proj weights with attention ----------------
__global__ __launch_bounds__(192) void fuseW(const float* __restrict__ proj_w,
                                             const float* __restrict__ attn,
                                             __half* __restrict__ w2)
{
    int bh = blockIdx.x;
    int h = bh % HEADS, b = bh / HEADS;
    __shared__ float At[CH][CH];
    const float* am = attn + (size_t)bh * CH * CH;
    for (int i = threadIdx.x; i < CH * CH; i += 192)
        At[i / CH][i % CH] = am[i];
    __syncthreads();

    int o = threadIdx.x;
    float pr[CH];
    #pragma unroll
    for (int c = 0; c < CH; c++) pr[c] = proj_w[(size_t)o * C + h * CH + c];

    __half* dst = w2 + (size_t)b * C * C + (size_t)o * C + h * CH;
    #pragma unroll 4
    for (int e = 0; e < CH; e++) {
        float acc = 0.f;
        #pragma unroll
        for (int c = 0; c < CH; c++) acc += pr[c] * At[c][e];
        dst[e] = __float2half_rn(acc);
    }
}

// ---------------- launch ----------------
extern "C" void kernel_launch(void* const* d_in, const int* in_sizes, int n_in,
                              void* d_out, int out_size)
{
    const float* x      = (const float*)d_in[0];
    const float* qkv_w  = (const float*)d_in[1];
    const float* qkv_b  = (const float*)d_in[2];
    const float* dw_w   = (const float*)d_in[3];
    const float* dw_b   = (const float*)d_in[4];
    const float* proj_w = (const float*)d_in[5];
    const float* proj_b = (const float*)d_in[6];
    const float* temp   = (const float*)d_in[7];
    float* out = (float*)d_out;

    float *ssqp, *atp;
    __half *qkvhp, *dwhp, *whp, *w2p;
    cudaGetSymbolAddress((void**)&qkvhp, g_qkvh);
    cudaGetSymbolAddress((void**)&dwhp,  g_dwh);
    cudaGetSymbolAddress((void**)&ssqp,  g_ssq);
    cudaGetSymbolAddress((void**)&atp,   g_at);
    cudaGetSymbolAddress((void**)&whp,   g_wh);
    cudaGetSymbolAddress((void**)&w2p,   g_w2h);

    cudaFuncSetAttribute(qk_mma, cudaFuncAttributeMaxDynamicSharedMemorySize, QK_SMEM);

    // 0) qkv weights -> fp16, zero attn accumulator
    cvtW<<<(C3 * C + B * HEADS * CH * CH + 255) / 256, 256>>>(qkv_w, whp, atp);
    // 1) qkv 1x1 conv (fp16 tensor core), fp16 output; o-tiles on grid.x for L2 X reuse
    gemm_mma<0, 1><<<dim3(C3 / BMg, NPTS / BNg, B), 512>>>(
        x, (size_t)C * NPTS, whp, 0, qkv_b, qkvhp, (size_t)C3 * NPTS);
    // 2) depthwise 3x3x3 (fp16 in -> fp16 out, + ssq of rounded q/k)
    dwconv3<<<B * C3, 256>>>(qkvhp, dw_w, dw_b, dwhp, ssqp);
    // 3) q @ k^T via fp16 tensor cores
    qk_mma<<<dim3(QK_NSPL, HEADS, B), 256, QK_SMEM>>>(dwhp, atp);
    // 4) scale + softmax
    softmaxk<<<(B * HEADS * CH + 7) / 8, 256>>>(atp, ssqp, temp);
    // 5) fuse proj with attention
    fuseW<<<B * HEADS, 192>>>(proj_w, atp, w2p);
    // 6) fused (proj∘attn) @ v (fp16 v read directly)
    gemm_mma<1, 0><<<dim3(1, NPTS / BNg, B), 512>>>(
        dwhp + (size_t)2 * C * NPTS, (size_t)C3 * NPTS,
        w2p, (size_t)C * C, proj_b, out, (size_t)C * NPTS);
}

// round 8
// speedup vs baseline: 1.0221x; 1.0221x over previous
#include <cuda_runtime.h>
#include <cuda_fp16.h>
#include <cstdint>

#define B 2
#define C 192
#define C3 576
#define SDIM 32
#define NPTS 32768           // 32^3
#define HEADS 4
#define CH 48
#define EPS 1e-12f

// ---------------- scratch (static device allocations) ----------------
__device__ __half g_qkvh[(size_t)B * C3 * NPTS];     // after 1x1 conv (fp16)
__device__ __half g_dwh [(size_t)B * C3 * NPTS];     // after dwconv: q,k,v fp16
__device__ float  g_ssq[B * 2 * C];                  // sum of squares of ROUNDED q/k
__device__ float  g_at [B * HEADS * CH * CH];        // attention logits / probs
__device__ __half g_wh [C3 * C];                     // qkv weights fp16
__device__ __half g_w2h[B * C * C];                  // fused proj∘attn weights fp16

// ================= mma.sync helpers =================
__device__ __forceinline__ uint32_t smem_u32(const void* p) {
    uint32_t a;
    asm("{ .reg .u64 t; cvta.to.shared.u64 t, %1; cvt.u32.u64 %0, t; }" : "=r"(a) : "l"(p));
    return a;
}
__device__ __forceinline__ void ldsm4(uint32_t* r, uint32_t a) {
    asm volatile("ldmatrix.sync.aligned.m8n8.x4.shared.b16 {%0,%1,%2,%3}, [%4];"
                 : "=r"(r[0]), "=r"(r[1]), "=r"(r[2]), "=r"(r[3]) : "r"(a));
}
__device__ __forceinline__ void ldsm4t(uint32_t* r, uint32_t a) {
    asm volatile("ldmatrix.sync.aligned.m8n8.x4.trans.shared.b16 {%0,%1,%2,%3}, [%4];"
                 : "=r"(r[0]), "=r"(r[1]), "=r"(r[2]), "=r"(r[3]) : "r"(a));
}
__device__ __forceinline__ void mma_f16(float* d, const uint32_t* a, const uint32_t* b) {
    asm volatile(
        "mma.sync.aligned.m16n8k16.row.col.f32.f16.f16.f32 "
        "{%0,%1,%2,%3}, {%4,%5,%6,%7}, {%8,%9}, {%0,%1,%2,%3};"
        : "+f"(d[0]), "+f"(d[1]), "+f"(d[2]), "+f"(d[3])
        : "r"(a[0]), "r"(a[1]), "r"(a[2]), "r"(a[3]), "r"(b[0]), "r"(b[1]));
}
__device__ __forceinline__ uint2 cvt4h(const float4 v) {
    __half2 h0 = __floats2half2_rn(v.x, v.y);
    __half2 h1 = __floats2half2_rn(v.z, v.w);
    uint2 r;
    r.x = *reinterpret_cast<uint32_t*>(&h0);
    r.y = *reinterpret_cast<uint32_t*>(&h1);
    return r;
}
#define CP_ASYNC16(dst, src) \
    asm volatile("cp.async.ca.shared.global [%0], [%1], 16;" :: "r"(dst), "l"(src))
#define CP_COMMIT() asm volatile("cp.async.commit_group;")

// ---------------- setup kernels (3 launches so gemm_mma is launch #4 for ncu) ----
__global__ void cvtWpart(const float* __restrict__ src, __half* __restrict__ dst,
                         int off, int n)
{
    int i = blockIdx.x * 256 + threadIdx.x;
    if (i < n) dst[off + i] = __float2half_rn(src[off + i]);
}
__global__ void zeroAt(float* __restrict__ attn)
{
    int i = blockIdx.x * 256 + threadIdx.x;
    if (i < B * HEADS * CH * CH) attn[i] = 0.f;
}

// ---------------- 1x1 conv GEMM via fp16 mma.sync ----------------
#define BMg 192
#define BNg 128
#define BKg 32
#define PA 40
#define PB 136

template<int XHALF, int OHALF>
__global__ __launch_bounds__(512) void gemm_mma(
    const void* __restrict__ Xall, size_t xbs,
    const __half* __restrict__ WH, size_t wbs,
    const float* __restrict__ bias, void* __restrict__ Yall, size_t ybs)
{
    __shared__ __align__(16) uint16_t sA[BMg * PA];
    __shared__ __align__(16) uint16_t sB[BKg * PB];

    const int tid = threadIdx.x, wid = tid >> 5, lane = tid & 31;
    const int o0 = blockIdx.x * BMg;
    const int n0 = blockIdx.y * BNg;
    const __half* W = WH + (size_t)blockIdx.z * wbs;

    const int warp_m = (wid >> 2) * 48;
    const int warp_n = (wid & 3) * 32;

    const uint32_t bA = smem_u32(sA);
    const uint32_t bB = smem_u32(sB);
    const uint32_t aOff = ((warp_m + (lane & 15)) * PA + (lane >> 4) * 8) * 2;

    float acc[3][4][4] = {};

    for (int kc = 0; kc < C; kc += BKg) {
        #pragma unroll
        for (int q = 0; q < 3; q++) {
            int t = tid + q * 512;
            int m = t >> 3, k4 = (t & 7) * 4;
            *reinterpret_cast<uint2*>(&sA[m * PA + k4]) =
                *reinterpret_cast<const uint2*>(&W[(size_t)(o0 + m) * C + kc + k4]);
        }
        if (XHALF) {
            const __half* X = (const __half*)Xall + (size_t)blockIdx.z * xbs;
            #pragma unroll
            for (int q = 0; q < 2; q++) {
                int t = tid + q * 512;
                int c = t >> 5, n4 = (t & 31) * 4;
                *reinterpret_cast<uint2*>(&sB[c * PB + n4]) = *reinterpret_cast<const uint2*>(
                    &X[(size_t)(kc + c) * NPTS + n0 + n4]);
            }
        } else {
            const float* X = (const float*)Xall + (size_t)blockIdx.z * xbs;
            #pragma unroll
            for (int q = 0; q < 2; q++) {
                int t = tid + q * 512;
                int c = t >> 5, n4 = (t & 31) * 4;
                float4 xv = *reinterpret_cast<const float4*>(&X[(size_t)(kc + c) * NPTS + n0 + n4]);
                *reinterpret_cast<uint2*>(&sB[c * PB + n4]) = cvt4h(xv);
            }
        }
        __syncthreads();

        #pragma unroll
        for (int ks = 0; ks < 2; ks++) {
            uint32_t Bf[4][2];
            #pragma unroll
            for (int jj = 0; jj < 2; jj++) {   // x4 trans: two j-frags per ldmatrix
                uint32_t r[4];
                uint32_t off = (((lane & 15) + ks * 16) * PB +
                                warp_n + jj * 16 + (lane >> 4) * 8) * 2;
                ldsm4t(r, bB + off);
                Bf[2 * jj][0] = r[0]; Bf[2 * jj][1] = r[1];
                Bf[2 * jj + 1][0] = r[2]; Bf[2 * jj + 1][1] = r[3];
            }
            #pragma unroll
            for (int i = 0; i < 3; i++) {
                uint32_t Af[4];
                ldsm4(Af, bA + aOff + i * (16 * PA * 2) + ks * 32);
                #pragma unroll
                for (int j = 0; j < 4; j++)
                    mma_f16(acc[i][j], Af, Bf[j]);
            }
        }
        __syncthreads();
    }

    #pragma unroll
    for (int i = 0; i < 3; i++) {
        int m = o0 + warp_m + i * 16 + (lane >> 2);
        float bv0 = bias[m], bv1 = bias[m + 8];
        #pragma unroll
        for (int j = 0; j < 4; j++) {
            int n = n0 + warp_n + j * 8 + (lane & 3) * 2;
            if (OHALF) {
                __half* Y = (__half*)Yall + (size_t)blockIdx.z * ybs;
                __half2 r0 = __floats2half2_rn(acc[i][j][0] + bv0, acc[i][j][1] + bv0);
                __half2 r1 = __floats2half2_rn(acc[i][j][2] + bv1, acc[i][j][3] + bv1);
                *reinterpret_cast<__half2*>(&Y[(size_t)m * NPTS + n]) = r0;
                *reinterpret_cast<__half2*>(&Y[(size_t)(m + 8) * NPTS + n]) = r1;
            } else {
                float* Y = (float*)Yall + (size_t)blockIdx.z * ybs;
                float2 r0 = {acc[i][j][0] + bv0, acc[i][j][1] + bv0};
                float2 r1 = {acc[i][j][2] + bv1, acc[i][j][3] + bv1};
                *reinterpret_cast<float2*>(&Y[(size_t)m * NPTS + n]) = r0;
                *reinterpret_cast<float2*>(&Y[(size_t)(m + 8) * NPTS + n]) = r1;
            }
        }
    }
}

// ---------------- depthwise 3x3x3 (fp16 in) -> fp16 q,k,v + ssq of rounded q/k ------
// 4-plane ring: written slot never among the 3 read slots -> ONE sync per z
__global__ __launch_bounds__(256) void dwconv3(
    const __half* __restrict__ in, const float* __restrict__ w,
    const float* __restrict__ bias, __half* __restrict__ outh,
    float* __restrict__ ssq)
{
    int bc = blockIdx.x;
    int b  = bc / C3;
    int c  = bc % C3;
    const __half* vol = in + (size_t)bc * NPTS;
    __half* op = outh + (size_t)bc * NPTS;

    float wr[27];
    #pragma unroll
    for (int i = 0; i < 27; i++) wr[i] = w[c * 27 + i];
    float bv = bias[c];

    __shared__ float P[4][34][36];
    __shared__ float sred[8];
    int tid = threadIdx.x;
    for (int i = tid; i < 4 * 34 * 36; i += 256) ((float*)P)[i] = 0.f;
    __syncthreads();
    {
        int y = tid >> 3, x4 = (tid & 7) * 4;
        uint2 raw = *reinterpret_cast<const uint2*>(&vol[y * 32 + x4]);
        __half2 hA = *reinterpret_cast<__half2*>(&raw.x);
        __half2 hB = *reinterpret_cast<__half2*>(&raw.y);
        P[0][1 + y][1 + x4 + 0] = __half2float(hA.x);
        P[0][1 + y][1 + x4 + 1] = __half2float(hA.y);
        P[0][1 + y][1 + x4 + 2] = __half2float(hB.x);
        P[0][1 + y][1 + x4 + 3] = __half2float(hB.y);
    }
    __syncthreads();

    int tx4 = (tid & 7) * 4;
    int ty  = tid >> 3;
    float qs = 0.f;
    const bool is_qk = (c < 2 * C);

    for (int z = 0; z < SDIM; z++) {
        int nb = (z + 1) & 3;
        if (z + 1 < SDIM) {
            int y = tid >> 3, x4 = (tid & 7) * 4;
            uint2 raw = *reinterpret_cast<const uint2*>(&vol[(size_t)(z + 1) * 1024 + y * 32 + x4]);
            __half2 hA = *reinterpret_cast<__half2*>(&raw.x);
            __half2 hB = *reinterpret_cast<__half2*>(&raw.y);
            P[nb][1 + y][1 + x4 + 0] = __half2float(hA.x);
            P[nb][1 + y][1 + x4 + 1] = __half2float(hA.y);
            P[nb][1 + y][1 + x4 + 2] = __half2float(hB.x);
            P[nb][1 + y][1 + x4 + 3] = __half2float(hB.y);
        } else {
            for (int i = tid; i < 34 * 36; i += 256) ((float*)P[nb])[i] = 0.f;
        }
        __syncthreads();
        int pm = (z + 3) & 3;
        int pc = z & 3;
        float a0 = bv, a1 = bv, a2 = bv, a3 = bv;
        #pragma unroll
        for (int dz = 0; dz < 3; dz++) {
            int pi = (dz == 0) ? pm : (dz == 1) ? pc : nb;
            #pragma unroll
            for (int dy = 0; dy < 3; dy++) {
                const float* row = &P[pi][ty + dy][tx4];
                float4 rA = *reinterpret_cast<const float4*>(row);
                float2 rB = *reinterpret_cast<const float2*>(row + 4);
                float w0 = wr[dz * 9 + dy * 3 + 0];
                float w1 = wr[dz * 9 + dy * 3 + 1];
                float w2 = wr[dz * 9 + dy * 3 + 2];
                a0 += w0 * rA.x + w1 * rA.y + w2 * rA.z;
                a1 += w0 * rA.y + w1 * rA.z + w2 * rA.w;
                a2 += w0 * rA.z + w1 * rA.w + w2 * rB.x;
                a3 += w0 * rA.w + w1 * rB.x + w2 * rB.y;
            }
        }
        size_t off = (size_t)z * 1024 + ty * 32 + tx4;
        __half2 h0 = __floats2half2_rn(a0, a1);
        __half2 h1 = __floats2half2_rn(a2, a3);
        uint2 hv = {*reinterpret_cast<uint32_t*>(&h0), *reinterpret_cast<uint32_t*>(&h1)};
        *reinterpret_cast<uint2*>(&op[off]) = hv;
        if (is_qk) {
            float r0 = __half2float(h0.x), r1 = __half2float(h0.y);
            float r2 = __half2float(h1.x), r3 = __half2float(h1.y);
            qs += r0 * r0 + r1 * r1 + r2 * r2 + r3 * r3;
        }
    }

    if (is_qk) {
        #pragma unroll
        for (int o = 16; o > 0; o >>= 1) qs += __shfl_xor_sync(~0u, qs, o);
        if ((tid & 31) == 0) sred[tid >> 5] = qs;
        __syncthreads();
        if (tid < 8) {
            float v = sred[tid];
            #pragma unroll
            for (int o = 4; o > 0; o >>= 1) v += __shfl_xor_sync(0xffu, v, o);
            if (tid == 0) ssq[b * 2 * C + c] = v;
        }
    }
}

// ---------------- q @ k^T via fp16 mma.sync ----------------
#define QKC 128                      // k-chunk per stage
#define QKP 136                      // smem pitch in halfs
#define QK_ARR (48 * QKP * 2)        // bytes per array (13056)
#define QK_STAGE (2 * QK_ARR)        // Q, K
#define QK_NSPL 32
#define QK_SLAB (NPTS / QK_NSPL)     // 1024
#define QK_SMEM (2 * QK_STAGE + 48 * 49 * 4)

__global__ __launch_bounds__(256) void qk_mma(
    const __half* __restrict__ dwh, float* __restrict__ attn)
{
    extern __shared__ char smem[];
    float* sAcc = reinterpret_cast<float*>(smem + 2 * QK_STAGE);
    const int tid = threadIdx.x, wid = tid >> 5, lane = tid & 31;
    const int b = blockIdx.z, h = blockIdx.y;
    const int n0 = blockIdx.x * QK_SLAB;

    const __half* srcs[2] = {
        dwh + ((size_t)b * C3 + h * CH) * NPTS,        // Q
        dwh + ((size_t)b * C3 + C + h * CH) * NPTS     // K
    };
    const uint32_t sbase = smem_u32(smem);

    for (int i = tid; i < 48 * 49; i += 256) sAcc[i] = 0.f;

    int la[6], lr[6], lc[6];
    #pragma unroll
    for (int q = 0; q < 6; q++) {
        int idx = tid + q * 256;
        la[q] = idx / 768;
        int rem = idx % 768;
        lr[q] = rem / 16;
        lc[q] = (rem % 16) * 8;
    }

    const int NCH = QK_SLAB / QKC;       // 8
    #pragma unroll
    for (int q = 0; q < 6; q++) {
        uint32_t dst = sbase + la[q] * QK_ARR + (lr[q] * QKP + lc[q]) * 2;
        CP_ASYNC16(dst, srcs[la[q]] + (size_t)lr[q] * NPTS + n0 + lc[q]);
    }
    CP_COMMIT();

    float acc[3][6][4] = {};
    const int k0 = wid * 16;

    for (int ch = 0; ch < NCH; ch++) {
        if (ch + 1 < NCH) {
            uint32_t st = ((ch + 1) & 1) * QK_STAGE;
            int nb = n0 + (ch + 1) * QKC;
            #pragma unroll
            for (int q = 0; q < 6; q++) {
                uint32_t dst = sbase + st + la[q] * QK_ARR + (lr[q] * QKP + lc[q]) * 2;
                CP_ASYNC16(dst, srcs[la[q]] + (size_t)lr[q] * NPTS + nb + lc[q]);
            }
            CP_COMMIT();
            asm volatile("cp.async.wait_group 1;");
        } else {
            asm volatile("cp.async.wait_group 0;");
        }
        __syncthreads();

        const uint32_t st = sbase + (ch & 1) * QK_STAGE;
        uint32_t Af[3][4], Bf[6][2];
        #pragma unroll
        for (int i = 0; i < 3; i++) {
            uint32_t off = ((i * 16 + (lane & 15)) * QKP + k0 + (lane >> 4) * 8) * 2;
            ldsm4(Af[i], st + off);
        }
        #pragma unroll
        for (int jj = 0; jj < 3; jj++) {   // x4: two n8k16 frags per ldmatrix
            uint32_t r[4];
            uint32_t off = ((jj * 16 + (lane & 7) + ((lane >> 4) << 3)) * QKP +
                            k0 + ((lane >> 3) & 1) * 8) * 2;
            ldsm4(r, st + QK_ARR + off);
            Bf[2 * jj][0] = r[0]; Bf[2 * jj][1] = r[1];
            Bf[2 * jj + 1][0] = r[2]; Bf[2 * jj + 1][1] = r[3];
        }
        #pragma unroll
        for (int i = 0; i < 3; i++)
            #pragma unroll
            for (int j = 0; j < 6; j++)
                mma_f16(acc[i][j], Af[i], Bf[j]);
        __syncthreads();
    }

    #pragma unroll
    for (int i = 0; i < 3; i++) {
        int m = i * 16 + (lane >> 2);
        #pragma unroll
        for (int j = 0; j < 6; j++) {
            int n = j * 8 + (lane & 3) * 2;
            atomicAdd(&sAcc[m * 49 + n],           acc[i][j][0]);
            atomicAdd(&sAcc[m * 49 + n + 1],       acc[i][j][1]);
            atomicAdd(&sAcc[(m + 8) * 49 + n],     acc[i][j][2]);
            atomicAdd(&sAcc[(m + 8) * 49 + n + 1], acc[i][j][3]);
        }
    }
    __syncthreads();
    float* dst = attn + (size_t)(b * HEADS + h) * CH * CH;
    for (int i = tid; i < CH * CH; i += 256)
        atomicAdd(&dst[i], sAcc[(i / CH) * 49 + (i % CH)]);
}

// ---------------- scale + softmax ----------------
__global__ void softmaxk(float* __restrict__ attn, const float* __restrict__ ssq,
                         const float* __restrict__ temp)
{
    int gw = blockIdx.x * (blockDim.x / 32) + (threadIdx.x >> 5);
    if (gw >= B * HEADS * CH) return;
    int lane = threadIdx.x & 31;
    int c = gw % CH, bh = gw / CH, h = bh % HEADS, b = bh / HEADS;
    float* row = attn + (size_t)gw * CH;
    float iq = 1.f / fmaxf(sqrtf(ssq[b * 2 * C + h * CH + c]), EPS);
    float t  = temp[h];
    int e0 = lane, e1 = lane + 32;
    float ik0 = 1.f / fmaxf(sqrtf(ssq[b * 2 * C + C + h * CH + e0]), EPS);
    float x0 = row[e0] * iq * ik0 * t;
    float x1 = -1e30f;
    if (e1 < CH) {
        float ik1 = 1.f / fmaxf(sqrtf(ssq[b * 2 * C + C + h * CH + e1]), EPS);
        x1 = row[e1] * iq * ik1 * t;
    }
    float m = fmaxf(x0, x1);
    #pragma unroll
    for (int o = 16; o > 0; o >>= 1) m = fmaxf(m, __shfl_xor_sync(~0u, m, o));
    float ex0 = expf(x0 - m);
    float ex1 = (e1 < CH) ? expf(x1 - m) : 0.f;
    float s = ex0 + ex1;
    #pragma unroll
    for (int o = 16; o > 0; o >>= 1) s += __shfl_xor_sync(~0u, s, o);
    float r = 1.f / s;
    row[e0] = ex0 * r;
    if (e1 < CH) row[e1] = ex1 * r;
}

// ---------------- fuse proj weights with attention ----------------
__global__ __launch_bounds__(192) void fuseW(const float* __restrict__ proj_w,
                                             const float* __restrict__ attn,
                                             __half* __restrict__ w2)
{
    int bh = blockIdx.x;
    int h = bh % HEADS, b = bh / HEADS;
    __shared__ float At[CH][CH];
    const float* am = attn + (size_t)bh * CH * CH;
    for (int i = threadIdx.x; i < CH * CH; i += 192)
        At[i / CH][i % CH] = am[i];
    __syncthreads();

    int o = threadIdx.x;
    float pr[CH];
    #pragma unroll
    for (int c = 0; c < CH; c++) pr[c] = proj_w[(size_t)o * C + h * CH + c];

    __half* dst = w2 + (size_t)b * C * C + (size_t)o * C + h * CH;
    #pragma unroll 4
    for (int e = 0; e < CH; e++) {
        float acc = 0.f;
        #pragma unroll
        for (int c = 0; c < CH; c++) acc += pr[c] * At[c][e];
        dst[e] = __float2half_rn(acc);
    }
}

// ---------------- launch ----------------
extern "C" void kernel_launch(void* const* d_in, const int* in_sizes, int n_in,
                              void* d_out, int out_size)
{
    const float* x      = (const float*)d_in[0];
    const float* qkv_w  = (const float*)d_in[1];
    const float* qkv_b  = (const float*)d_in[2];
    const float* dw_w   = (const float*)d_in[3];
    const float* dw_b   = (const float*)d_in[4];
    const float* proj_w = (const float*)d_in[5];
    const float* proj_b = (const float*)d_in[6];
    const float* temp   = (const float*)d_in[7];
    float* out = (float*)d_out;

    float *ssqp, *atp;
    __half *qkvhp, *dwhp, *whp, *w2p;
    cudaGetSymbolAddress((void**)&qkvhp, g_qkvh);
    cudaGetSymbolAddress((void**)&dwhp,  g_dwh);
    cudaGetSymbolAddress((void**)&ssqp,  g_ssq);
    cudaGetSymbolAddress((void**)&atp,   g_at);
    cudaGetSymbolAddress((void**)&whp,   g_wh);
    cudaGetSymbolAddress((void**)&w2p,   g_w2h);

    cudaFuncSetAttribute(qk_mma, cudaFuncAttributeMaxDynamicSharedMemorySize, QK_SMEM);

    const int TW = C3 * C;
    // 1-3) setup split into 3 launches (puts gemm_mma at launch #4 = ncu capture slot)
    cvtWpart<<<(TW / 2 + 255) / 256, 256>>>(qkv_w, whp, 0, TW / 2);
    cvtWpart<<<(TW / 2 + 255) / 256, 256>>>(qkv_w, whp, TW / 2, TW - TW / 2);
    zeroAt<<<(B * HEADS * CH * CH + 255) / 256, 256>>>(atp);
    // 4) qkv 1x1 conv (fp16 tensor core) <- PROFILED
    gemm_mma<0, 1><<<dim3(C3 / BMg, NPTS / BNg, B), 512>>>(
        x, (size_t)C * NPTS, whp, 0, qkv_b, qkvhp, (size_t)C3 * NPTS);
    // 5) depthwise 3x3x3
    dwconv3<<<B * C3, 256>>>(qkvhp, dw_w, dw_b, dwhp, ssqp);
    // 6) q @ k^T
    qk_mma<<<dim3(QK_NSPL, HEADS, B), 256, QK_SMEM>>>(dwhp, atp);
    // 7) scale + softmax
    softmaxk<<<(B * HEADS * CH + 7) / 8, 256>>>(atp, ssqp, temp);
    // 8) fuse proj with attention
    fuseW<<<B * HEADS, 192>>>(proj_w, atp, w2p);
    // 9) fused (proj∘attn) @ v
    gemm_mma<1, 0><<<dim3(1, NPTS / BNg, B), 512>>>(
        dwhp + (size_t)2 * C * NPTS, (size_t)C3 * NPTS,
        w2p, (size_t)C * C, proj_b, out, (size_t)C * NPTS);
}

// round 9
// speedup vs baseline: 1.1492x; 1.1244x over previous
#include <cuda_runtime.h>
#include <cuda_fp16.h>
#include <cstdint>

#define B 2
#define C 192
#define C3 576
#define SDIM 32
#define NPTS 32768           // 32^3
#define HEADS 4
#define CH 48
#define EPS 1e-12f

// ---------------- scratch (static device allocations) ----------------
__device__ __half g_xh  [(size_t)B * C * NPTS];      // input x in fp16
__device__ __half g_qkvh[(size_t)B * C3 * NPTS];     // after 1x1 conv (fp16)
__device__ __half g_dwh [(size_t)B * C3 * NPTS];     // after dwconv: q,k,v fp16
__device__ float  g_ssq[B * 2 * C];                  // sum of squares of ROUNDED q/k
__device__ float  g_at [B * HEADS * CH * CH];        // attention logits / probs
__device__ __half g_wh [C3 * C];                     // qkv weights fp16
__device__ __half g_w2h[B * C * C];                  // fused proj∘attn weights fp16

// ================= mma.sync helpers =================
__device__ __forceinline__ uint32_t smem_u32(const void* p) {
    uint32_t a;
    asm("{ .reg .u64 t; cvta.to.shared.u64 t, %1; cvt.u32.u64 %0, t; }" : "=r"(a) : "l"(p));
    return a;
}
__device__ __forceinline__ void ldsm4(uint32_t* r, uint32_t a) {
    asm volatile("ldmatrix.sync.aligned.m8n8.x4.shared.b16 {%0,%1,%2,%3}, [%4];"
                 : "=r"(r[0]), "=r"(r[1]), "=r"(r[2]), "=r"(r[3]) : "r"(a));
}
__device__ __forceinline__ void ldsm4t(uint32_t* r, uint32_t a) {
    asm volatile("ldmatrix.sync.aligned.m8n8.x4.trans.shared.b16 {%0,%1,%2,%3}, [%4];"
                 : "=r"(r[0]), "=r"(r[1]), "=r"(r[2]), "=r"(r[3]) : "r"(a));
}
__device__ __forceinline__ void mma_f16(float* d, const uint32_t* a, const uint32_t* b) {
    asm volatile(
        "mma.sync.aligned.m16n8k16.row.col.f32.f16.f16.f32 "
        "{%0,%1,%2,%3}, {%4,%5,%6,%7}, {%8,%9}, {%0,%1,%2,%3};"
        : "+f"(d[0]), "+f"(d[1]), "+f"(d[2]), "+f"(d[3])
        : "r"(a[0]), "r"(a[1]), "r"(a[2]), "r"(a[3]), "r"(b[0]), "r"(b[1]));
}
#define CP_ASYNC16(dst, src) \
    asm volatile("cp.async.ca.shared.global [%0], [%1], 16;" :: "r"(dst), "l"(src))
#define CP_COMMIT() asm volatile("cp.async.commit_group;")

// ---------------- setup kernels ----------------
__global__ void cvtW(const float* __restrict__ qkv_w, __half* __restrict__ wh)
{
    int i = blockIdx.x * 256 + threadIdx.x;
    if (i < C3 * C) wh[i] = __float2half_rn(qkv_w[i]);
}
__global__ void cvtX(const float* __restrict__ x, __half* __restrict__ xh)
{
    size_t i = ((size_t)blockIdx.x * 256 + threadIdx.x) * 4;   // total = B*C*NPTS
    float4 v = *reinterpret_cast<const float4*>(&x[i]);
    __half2 h0 = __floats2half2_rn(v.x, v.y);
    __half2 h1 = __floats2half2_rn(v.z, v.w);
    uint2 r = {*reinterpret_cast<uint32_t*>(&h0), *reinterpret_cast<uint32_t*>(&h1)};
    *reinterpret_cast<uint2*>(&xh[i]) = r;
}
__global__ void zeroAt(float* __restrict__ attn)
{
    int i = blockIdx.x * 256 + threadIdx.x;
    if (i < B * HEADS * CH * CH) attn[i] = 0.f;
}

// ---------------- 1x1 conv GEMM via fp16 mma.sync, cp.async double-buffered -------
#define BMg 192
#define BNg 128
#define BKg 32
#define PA 40
#define PB 136
#define SA_BYTES (BMg * PA * 2)
#define SB_BYTES (BKg * PB * 2)

template<int OHALF>
__global__ __launch_bounds__(512) void gemm_mma(
    const __half* __restrict__ Xall, size_t xbs,
    const __half* __restrict__ WH, size_t wbs,
    const float* __restrict__ bias, void* __restrict__ Yall, size_t ybs)
{
    __shared__ __align__(16) uint16_t sA[2][BMg * PA];
    __shared__ __align__(16) uint16_t sB[2][BKg * PB];

    const int tid = threadIdx.x, wid = tid >> 5, lane = tid & 31;
    const int o0 = blockIdx.x * BMg;
    const int n0 = blockIdx.y * BNg;
    const __half* X = Xall + (size_t)blockIdx.z * xbs;
    const __half* W = WH + (size_t)blockIdx.z * wbs;

    const int warp_m = (wid >> 2) * 48;
    const int warp_n = (wid & 3) * 32;

    const uint32_t bA = smem_u32(sA);
    const uint32_t bB = smem_u32(sB);
    const uint32_t aOff = ((warp_m + (lane & 15)) * PA + (lane >> 4) * 8) * 2;

    // per-thread cp.async slots
    const int ar0 = tid >> 2,          ac0 = (tid & 3) * 8;          // A chunk tid
    const int ar1 = (tid + 512) >> 2,  ac1 = ((tid + 512) & 3) * 8;  // A chunk tid+512 (tid<256)
    const int br  = tid >> 4,          bc  = (tid & 15) * 8;         // B chunk tid

    // prologue: stage 0 (kc = 0)
    CP_ASYNC16(bA + (ar0 * PA + ac0) * 2, &W[(size_t)(o0 + ar0) * C + ac0]);
    if (tid < 256)
        CP_ASYNC16(bA + (ar1 * PA + ac1) * 2, &W[(size_t)(o0 + ar1) * C + ac1]);
    CP_ASYNC16(bB + (br * PB + bc) * 2, &X[(size_t)br * NPTS + n0 + bc]);
    CP_COMMIT();

    float acc[3][4][4] = {};

    #pragma unroll
    for (int it = 0; it < C / BKg; it++) {
        if (it + 1 < C / BKg) {
            const int kc = (it + 1) * BKg;
            const uint32_t dA = bA + ((it + 1) & 1) * SA_BYTES;
            const uint32_t dB = bB + ((it + 1) & 1) * SB_BYTES;
            CP_ASYNC16(dA + (ar0 * PA + ac0) * 2, &W[(size_t)(o0 + ar0) * C + kc + ac0]);
            if (tid < 256)
                CP_ASYNC16(dA + (ar1 * PA + ac1) * 2, &W[(size_t)(o0 + ar1) * C + kc + ac1]);
            CP_ASYNC16(dB + (br * PB + bc) * 2, &X[(size_t)(kc + br) * NPTS + n0 + bc]);
            CP_COMMIT();
            asm volatile("cp.async.wait_group 1;");
        } else {
            asm volatile("cp.async.wait_group 0;");
        }
        __syncthreads();

        const uint32_t stA = bA + (it & 1) * SA_BYTES;
        const uint32_t stB = bB + (it & 1) * SB_BYTES;
        #pragma unroll
        for (int ks = 0; ks < 2; ks++) {
            uint32_t Bf[4][2];
            #pragma unroll
            for (int jj = 0; jj < 2; jj++) {
                uint32_t r[4];
                uint32_t off = (((lane & 15) + ks * 16) * PB +
                                warp_n + jj * 16 + (lane >> 4) * 8) * 2;
                ldsm4t(r, stB + off);
                Bf[2 * jj][0] = r[0]; Bf[2 * jj][1] = r[1];
                Bf[2 * jj + 1][0] = r[2]; Bf[2 * jj + 1][1] = r[3];
            }
            #pragma unroll
            for (int i = 0; i < 3; i++) {
                uint32_t Af[4];
                ldsm4(Af, stA + aOff + i * (16 * PA * 2) + ks * 32);
                #pragma unroll
                for (int j = 0; j < 4; j++)
                    mma_f16(acc[i][j], Af, Bf[j]);
            }
        }
        __syncthreads();
    }

    #pragma unroll
    for (int i = 0; i < 3; i++) {
        int m = o0 + warp_m + i * 16 + (lane >> 2);
        float bv0 = bias[m], bv1 = bias[m + 8];
        #pragma unroll
        for (int j = 0; j < 4; j++) {
            int n = n0 + warp_n + j * 8 + (lane & 3) * 2;
            if (OHALF) {
                __half* Y = (__half*)Yall + (size_t)blockIdx.z * ybs;
                __half2 r0 = __floats2half2_rn(acc[i][j][0] + bv0, acc[i][j][1] + bv0);
                __half2 r1 = __floats2half2_rn(acc[i][j][2] + bv1, acc[i][j][3] + bv1);
                *reinterpret_cast<__half2*>(&Y[(size_t)m * NPTS + n]) = r0;
                *reinterpret_cast<__half2*>(&Y[(size_t)(m + 8) * NPTS + n]) = r1;
            } else {
                float* Y = (float*)Yall + (size_t)blockIdx.z * ybs;
                float2 r0 = {acc[i][j][0] + bv0, acc[i][j][1] + bv0};
                float2 r1 = {acc[i][j][2] + bv1, acc[i][j][3] + bv1};
                *reinterpret_cast<float2*>(&Y[(size_t)m * NPTS + n]) = r0;
                *reinterpret_cast<float2*>(&Y[(size_t)(m + 8) * NPTS + n]) = r1;
            }
        }
    }
}

// ---------------- depthwise 3x3x3 (fp16 in) -> fp16 q,k,v + ssq of rounded q/k ------
__global__ __launch_bounds__(256) void dwconv3(
    const __half* __restrict__ in, const float* __restrict__ w,
    const float* __restrict__ bias, __half* __restrict__ outh,
    float* __restrict__ ssq)
{
    int bc = blockIdx.x;
    int b  = bc / C3;
    int c  = bc % C3;
    const __half* vol = in + (size_t)bc * NPTS;
    __half* op = outh + (size_t)bc * NPTS;

    float wr[27];
    #pragma unroll
    for (int i = 0; i < 27; i++) wr[i] = w[c * 27 + i];
    float bv = bias[c];

    __shared__ float P[4][34][36];
    __shared__ float sred[8];
    int tid = threadIdx.x;
    for (int i = tid; i < 4 * 34 * 36; i += 256) ((float*)P)[i] = 0.f;
    __syncthreads();
    {
        int y = tid >> 3, x4 = (tid & 7) * 4;
        uint2 raw = *reinterpret_cast<const uint2*>(&vol[y * 32 + x4]);
        __half2 hA = *reinterpret_cast<__half2*>(&raw.x);
        __half2 hB = *reinterpret_cast<__half2*>(&raw.y);
        P[0][1 + y][1 + x4 + 0] = __half2float(hA.x);
        P[0][1 + y][1 + x4 + 1] = __half2float(hA.y);
        P[0][1 + y][1 + x4 + 2] = __half2float(hB.x);
        P[0][1 + y][1 + x4 + 3] = __half2float(hB.y);
    }
    __syncthreads();

    int tx4 = (tid & 7) * 4;
    int ty  = tid >> 3;
    float qs = 0.f;
    const bool is_qk = (c < 2 * C);

    for (int z = 0; z < SDIM; z++) {
        int nb = (z + 1) & 3;
        if (z + 1 < SDIM) {
            int y = tid >> 3, x4 = (tid & 7) * 4;
            uint2 raw = *reinterpret_cast<const uint2*>(&vol[(size_t)(z + 1) * 1024 + y * 32 + x4]);
            __half2 hA = *reinterpret_cast<__half2*>(&raw.x);
            __half2 hB = *reinterpret_cast<__half2*>(&raw.y);
            P[nb][1 + y][1 + x4 + 0] = __half2float(hA.x);
            P[nb][1 + y][1 + x4 + 1] = __half2float(hA.y);
            P[nb][1 + y][1 + x4 + 2] = __half2float(hB.x);
            P[nb][1 + y][1 + x4 + 3] = __half2float(hB.y);
        } else {
            for (int i = tid; i < 34 * 36; i += 256) ((float*)P[nb])[i] = 0.f;
        }
        __syncthreads();
        int pm = (z + 3) & 3;
        int pc = z & 3;
        float a0 = bv, a1 = bv, a2 = bv, a3 = bv;
        #pragma unroll
        for (int dz = 0; dz < 3; dz++) {
            int pi = (dz == 0) ? pm : (dz == 1) ? pc : nb;
            #pragma unroll
            for (int dy = 0; dy < 3; dy++) {
                const float* row = &P[pi][ty + dy][tx4];
                float4 rA = *reinterpret_cast<const float4*>(row);
                float2 rB = *reinterpret_cast<const float2*>(row + 4);
                float w0 = wr[dz * 9 + dy * 3 + 0];
                float w1 = wr[dz * 9 + dy * 3 + 1];
                float w2 = wr[dz * 9 + dy * 3 + 2];
                a0 += w0 * rA.x + w1 * rA.y + w2 * rA.z;
                a1 += w0 * rA.y + w1 * rA.z + w2 * rA.w;
                a2 += w0 * rA.z + w1 * rA.w + w2 * rB.x;
                a3 += w0 * rA.w + w1 * rB.x + w2 * rB.y;
            }
        }
        size_t off = (size_t)z * 1024 + ty * 32 + tx4;
        __half2 h0 = __floats2half2_rn(a0, a1);
        __half2 h1 = __floats2half2_rn(a2, a3);
        uint2 hv = {*reinterpret_cast<uint32_t*>(&h0), *reinterpret_cast<uint32_t*>(&h1)};
        *reinterpret_cast<uint2*>(&op[off]) = hv;
        if (is_qk) {
            float r0 = __half2float(h0.x), r1 = __half2float(h0.y);
            float r2 = __half2float(h1.x), r3 = __half2float(h1.y);
            qs += r0 * r0 + r1 * r1 + r2 * r2 + r3 * r3;
        }
    }

    if (is_qk) {
        #pragma unroll
        for (int o = 16; o > 0; o >>= 1) qs += __shfl_xor_sync(~0u, qs, o);
        if ((tid & 31) == 0) sred[tid >> 5] = qs;
        __syncthreads();
        if (tid < 8) {
            float v = sred[tid];
            #pragma unroll
            for (int o = 4; o > 0; o >>= 1) v += __shfl_xor_sync(0xffu, v, o);
            if (tid == 0) ssq[b * 2 * C + c] = v;
        }
    }
}

// ---------------- q @ k^T via fp16 mma.sync ----------------
#define QKC 128
#define QKP 136
#define QK_ARR (48 * QKP * 2)
#define QK_STAGE (2 * QK_ARR)
#define QK_NSPL 32
#define QK_SLAB (NPTS / QK_NSPL)     // 1024
#define QK_SMEM (2 * QK_STAGE + 48 * 49 * 4)

__global__ __launch_bounds__(256) void qk_mma(
    const __half* __restrict__ dwh, float* __restrict__ attn)
{
    extern __shared__ char smem[];
    float* sAcc = reinterpret_cast<float*>(smem + 2 * QK_STAGE);
    const int tid = threadIdx.x, wid = tid >> 5, lane = tid & 31;
    const int b = blockIdx.z, h = blockIdx.y;
    const int n0 = blockIdx.x * QK_SLAB;

    const __half* srcs[2] = {
        dwh + ((size_t)b * C3 + h * CH) * NPTS,
        dwh + ((size_t)b * C3 + C + h * CH) * NPTS
    };
    const uint32_t sbase = smem_u32(smem);

    for (int i = tid; i < 48 * 49; i += 256) sAcc[i] = 0.f;

    int la[6], lr[6], lc[6];
    #pragma unroll
    for (int q = 0; q < 6; q++) {
        int idx = tid + q * 256;
        la[q] = idx / 768;
        int rem = idx % 768;
        lr[q] = rem / 16;
        lc[q] = (rem % 16) * 8;
    }

    const int NCH = QK_SLAB / QKC;
    #pragma unroll
    for (int q = 0; q < 6; q++) {
        uint32_t dst = sbase + la[q] * QK_ARR + (lr[q] * QKP + lc[q]) * 2;
        CP_ASYNC16(dst, srcs[la[q]] + (size_t)lr[q] * NPTS + n0 + lc[q]);
    }
    CP_COMMIT();

    float acc[3][6][4] = {};
    const int k0 = wid * 16;

    for (int ch = 0; ch < NCH; ch++) {
        if (ch + 1 < NCH) {
            uint32_t st = ((ch + 1) & 1) * QK_STAGE;
            int nb = n0 + (ch + 1) * QKC;
            #pragma unroll
            for (int q = 0; q < 6; q++) {
                uint32_t dst = sbase + st + la[q] * QK_ARR + (lr[q] * QKP + lc[q]) * 2;
                CP_ASYNC16(dst, srcs[la[q]] + (size_t)lr[q] * NPTS + nb + lc[q]);
            }
            CP_COMMIT();
            asm volatile("cp.async.wait_group 1;");
        } else {
            asm volatile("cp.async.wait_group 0;");
        }
        __syncthreads();

        const uint32_t st = sbase + (ch & 1) * QK_STAGE;
        uint32_t Af[3][4], Bf[6][2];
        #pragma unroll
        for (int i = 0; i < 3; i++) {
            uint32_t off = ((i * 16 + (lane & 15)) * QKP + k0 + (lane >> 4) * 8) * 2;
            ldsm4(Af[i], st + off);
        }
        #pragma unroll
        for (int jj = 0; jj < 3; jj++) {
            uint32_t r[4];
            uint32_t off = ((jj * 16 + (lane & 7) + ((lane >> 4) << 3)) * QKP +
                            k0 + ((lane >> 3) & 1) * 8) * 2;
            ldsm4(r, st + QK_ARR + off);
            Bf[2 * jj][0] = r[0]; Bf[2 * jj][1] = r[1];
            Bf[2 * jj + 1][0] = r[2]; Bf[2 * jj + 1][1] = r[3];
        }
        #pragma unroll
        for (int i = 0; i < 3; i++)
            #pragma unroll
            for (int j = 0; j < 6; j++)
                mma_f16(acc[i][j], Af[i], Bf[j]);
        __syncthreads();
    }

    #pragma unroll
    for (int i = 0; i < 3; i++) {
        int m = i * 16 + (lane >> 2);
        #pragma unroll
        for (int j = 0; j < 6; j++) {
            int n = j * 8 + (lane & 3) * 2;
            atomicAdd(&sAcc[m * 49 + n],           acc[i][j][0]);
            atomicAdd(&sAcc[m * 49 + n + 1],       acc[i][j][1]);
            atomicAdd(&sAcc[(m + 8) * 49 + n],     acc[i][j][2]);
            atomicAdd(&sAcc[(m + 8) * 49 + n + 1], acc[i][j][3]);
        }
    }
    __syncthreads();
    float* dst = attn + (size_t)(b * HEADS + h) * CH * CH;
    for (int i = tid; i < CH * CH; i += 256)
        atomicAdd(&dst[i], sAcc[(i / CH) * 49 + (i % CH)]);
}

// ---------------- scale + softmax ----------------
__global__ void softmaxk(float* __restrict__ attn, const float* __restrict__ ssq,
                         const float* __restrict__ temp)
{
    int gw = blockIdx.x * (blockDim.x / 32) + (threadIdx.x >> 5);
    if (gw >= B * HEADS * CH) return;
    int lane = threadIdx.x & 31;
    int c = gw % CH, bh = gw / CH, h = bh % HEADS, b = bh / HEADS;
    float* row = attn + (size_t)gw * CH;
    float iq = 1.f / fmaxf(sqrtf(ssq[b * 2 * C + h * CH + c]), EPS);
    float t  = temp[h];
    int e0 = lane, e1 = lane + 32;
    float ik0 = 1.f / fmaxf(sqrtf(ssq[b * 2 * C + C + h * CH + e0]), EPS);
    float x0 = row[e0] * iq * ik0 * t;
    float x1 = -1e30f;
    if (e1 < CH) {
        float ik1 = 1.f / fmaxf(sqrtf(ssq[b * 2 * C + C + h * CH + e1]), EPS);
        x1 = row[e1] * iq * ik1 * t;
    }
    float m = fmaxf(x0, x1);
    #pragma unroll
    for (int o = 16; o > 0; o >>= 1) m = fmaxf(m, __shfl_xor_sync(~0u, m, o));
    float ex0 = expf(x0 - m);
    float ex1 = (e1 < CH) ? expf(x1 - m) : 0.f;
    float s = ex0 + ex1;
    #pragma unroll
    for (int o = 16; o > 0; o >>= 1) s += __shfl_xor_sync(~0u, s, o);
    float r = 1.f / s;
    row[e0] = ex0 * r;
    if (e1 < CH) row[e1] = ex1 * r;
}

// ---------------- fuse proj weights with attention ----------------
__global__ __launch_bounds__(192) void fuseW(const float* __restrict__ proj_w,
                                             const float* __restrict__ attn,
                                             __half* __restrict__ w2)
{
    int bh = blockIdx.x;
    int h = bh % HEADS, b = bh / HEADS;
    __shared__ float At[CH][CH];
    const float* am = attn + (size_t)bh * CH * CH;
    for (int i = threadIdx.x; i < CH * CH; i += 192)
        At[i / CH][i % CH] = am[i];
    __syncthreads();

    int o = threadIdx.x;
    float pr[CH];
    #pragma unroll
    for (int c = 0; c < CH; c++) pr[c] = proj_w[(size_t)o * C + h * CH + c];

    __half* dst = w2 + (size_t)b * C * C + (size_t)o * C + h * CH;
    #pragma unroll 4
    for (int e = 0; e < CH; e++) {
        float acc = 0.f;
        #pragma unroll
        for (int c = 0; c < CH; c++) acc += pr[c] * At[c][e];
        dst[e] = __float2half_rn(acc);
    }
}

// ---------------- launch ----------------
extern "C" void kernel_launch(void* const* d_in, const int* in_sizes, int n_in,
                              void* d_out, int out_size)
{
    const float* x      = (const float*)d_in[0];
    const float* qkv_w  = (const float*)d_in[1];
    const float* qkv_b  = (const float*)d_in[2];
    const float* dw_w   = (const float*)d_in[3];
    const float* dw_b   = (const float*)d_in[4];
    const float* proj_w = (const float*)d_in[5];
    const float* proj_b = (const float*)d_in[6];
    const float* temp   = (const float*)d_in[7];
    float* out = (float*)d_out;

    float *ssqp, *atp;
    __half *xhp, *qkvhp, *dwhp, *whp, *w2p;
    cudaGetSymbolAddress((void**)&xhp,   g_xh);
    cudaGetSymbolAddress((void**)&qkvhp, g_qkvh);
    cudaGetSymbolAddress((void**)&dwhp,  g_dwh);
    cudaGetSymbolAddress((void**)&ssqp,  g_ssq);
    cudaGetSymbolAddress((void**)&atp,   g_at);
    cudaGetSymbolAddress((void**)&whp,   g_wh);
    cudaGetSymbolAddress((void**)&w2p,   g_w2h);

    cudaFuncSetAttribute(qk_mma, cudaFuncAttributeMaxDynamicSharedMemorySize, QK_SMEM);

    // 1) weights -> fp16
    cvtW<<<(C3 * C + 255) / 256, 256>>>(qkv_w, whp);
    // 2) x -> fp16
    cvtX<<<(int)((size_t)B * C * NPTS / 4 / 256), 256>>>(x, xhp);
    // 3) zero attn accumulator
    zeroAt<<<(B * HEADS * CH * CH + 255) / 256, 256>>>(atp);
    // 4) qkv 1x1 conv (cp.async pipelined fp16 tensor core) <- PROFILED
    gemm_mma<1><<<dim3(C3 / BMg, NPTS / BNg, B), 512>>>(
        xhp, (size_t)C * NPTS, whp, 0, qkv_b, qkvhp, (size_t)C3 * NPTS);
    // 5) depthwise 3x3x3
    dwconv3<<<B * C3, 256>>>(qkvhp, dw_w, dw_b, dwhp, ssqp);
    // 6) q @ k^T
    qk_mma<<<dim3(QK_NSPL, HEADS, B), 256, QK_SMEM>>>(dwhp, atp);
    // 7) scale + softmax
    softmaxk<<<(B * HEADS * CH + 7) / 8, 256>>>(atp, ssqp, temp);
    // 8) fuse proj with attention
    fuseW<<<B * HEADS, 192>>>(proj_w, atp, w2p);
    // 9) fused (proj∘attn) @ v
    gemm_mma<0><<<dim3(1, NPTS / BNg, B), 512>>>(
        dwhp + (size_t)2 * C * NPTS, (size_t)C3 * NPTS,
        w2p, (size_t)C * C, proj_b, out, (size_t)C * NPTS);
}

// round 10
// speedup vs baseline: 1.1635x; 1.0124x over previous
#include <cuda_runtime.h>
#include <cuda_fp16.h>
#include <cstdint>

#define B 2
#define C 192
#define C3 576
#define SDIM 32
#define NPTS 32768           // 32^3
#define HEADS 4
#define CH 48
#define EPS 1e-12f

// ---------------- scratch (static device allocations) ----------------
__device__ __half g_xh  [(size_t)B * C * NPTS];      // input x in fp16
__device__ __half g_qkvh[(size_t)B * C3 * NPTS];     // after 1x1 conv (fp16)
__device__ __half g_dwh [(size_t)B * C3 * NPTS];     // after dwconv: q,k,v fp16
__device__ float  g_ssq[B * 2 * C];                  // sum of squares of ROUNDED q/k
__device__ float  g_at [B * HEADS * CH * CH];        // attention logits / probs
__device__ __half g_wh [C3 * C];                     // qkv weights fp16
__device__ __half g_w2h[B * C * C];                  // fused proj∘attn weights fp16

// ================= mma.sync helpers =================
__device__ __forceinline__ uint32_t smem_u32(const void* p) {
    uint32_t a;
    asm("{ .reg .u64 t; cvta.to.shared.u64 t, %1; cvt.u32.u64 %0, t; }" : "=r"(a) : "l"(p));
    return a;
}
__device__ __forceinline__ void ldsm4(uint32_t* r, uint32_t a) {
    asm volatile("ldmatrix.sync.aligned.m8n8.x4.shared.b16 {%0,%1,%2,%3}, [%4];"
                 : "=r"(r[0]), "=r"(r[1]), "=r"(r[2]), "=r"(r[3]) : "r"(a));
}
__device__ __forceinline__ void ldsm4t(uint32_t* r, uint32_t a) {
    asm volatile("ldmatrix.sync.aligned.m8n8.x4.trans.shared.b16 {%0,%1,%2,%3}, [%4];"
                 : "=r"(r[0]), "=r"(r[1]), "=r"(r[2]), "=r"(r[3]) : "r"(a));
}
__device__ __forceinline__ void mma_f16(float* d, const uint32_t* a, const uint32_t* b) {
    asm volatile(
        "mma.sync.aligned.m16n8k16.row.col.f32.f16.f16.f32 "
        "{%0,%1,%2,%3}, {%4,%5,%6,%7}, {%8,%9}, {%0,%1,%2,%3};"
        : "+f"(d[0]), "+f"(d[1]), "+f"(d[2]), "+f"(d[3])
        : "r"(a[0]), "r"(a[1]), "r"(a[2]), "r"(a[3]), "r"(b[0]), "r"(b[1]));
}
#define CP_ASYNC16(dst, src) \
    asm volatile("cp.async.ca.shared.global [%0], [%1], 16;" :: "r"(dst), "l"(src))
#define CP_CG16(dst, src) \
    asm volatile("cp.async.cg.shared.global [%0], [%1], 16;" :: "r"(dst), "l"(src))
#define CP_COMMIT() asm volatile("cp.async.commit_group;")

// ---------------- setup kernels ----------------
__global__ void cvtWz(const float* __restrict__ qkv_w, __half* __restrict__ wh,
                      float* __restrict__ attn)
{
    int i = blockIdx.x * 256 + threadIdx.x;
    const int T0 = C3 * C;
    const int T1 = T0 + B * HEADS * CH * CH;
    if (i < T0)       wh[i] = __float2half_rn(qkv_w[i]);
    else if (i < T1)  attn[i - T0] = 0.f;
}
__global__ void cvtX(const float* __restrict__ x, __half* __restrict__ xh)
{
    size_t i = ((size_t)blockIdx.x * 256 + threadIdx.x) * 4;
    float4 v = *reinterpret_cast<const float4*>(&x[i]);
    __half2 h0 = __floats2half2_rn(v.x, v.y);
    __half2 h1 = __floats2half2_rn(v.z, v.w);
    uint2 r = {*reinterpret_cast<uint32_t*>(&h0), *reinterpret_cast<uint32_t*>(&h1)};
    *reinterpret_cast<uint2*>(&xh[i]) = r;
}

// ---------------- 1x1 conv GEMM via fp16 mma.sync, 3-stage cp.async.cg ------------
#define BMg 192
#define BNg 128
#define BKg 32
#define PA 40
#define PB 136
#define SA_BYTES (BMg * PA * 2)      // 15360
#define SB_BYTES (BKg * PB * 2)      // 8704
#define GM_SMEM  (3 * (SA_BYTES + SB_BYTES))   // 72192
#define NIT (C / BKg)                // 6

template<int OHALF>
__global__ __launch_bounds__(512) void gemm_mma(
    const __half* __restrict__ Xall, size_t xbs,
    const __half* __restrict__ WH, size_t wbs,
    const float* __restrict__ bias, void* __restrict__ Yall, size_t ybs)
{
    extern __shared__ char gsm[];
    const int tid = threadIdx.x, wid = tid >> 5, lane = tid & 31;
    const int o0 = blockIdx.x * BMg;
    const int n0 = blockIdx.y * BNg;
    const __half* X = Xall + (size_t)blockIdx.z * xbs;
    const __half* W = WH + (size_t)blockIdx.z * wbs;

    const int warp_m = (wid >> 2) * 48;
    const int warp_n = (wid & 3) * 32;

    const uint32_t bA = smem_u32(gsm);
    const uint32_t bB = bA + 3 * SA_BYTES;
    const uint32_t aOff = ((warp_m + (lane & 15)) * PA + (lane >> 4) * 8) * 2;

    const int ar0 = tid >> 2,          ac0 = (tid & 3) * 8;
    const int ar1 = (tid + 512) >> 2,  ac1 = ((tid + 512) & 3) * 8;
    const int br  = tid >> 4,          bc  = (tid & 15) * 8;

    auto prefetch = [&](int it) {
        const int kc = it * BKg;
        const int s  = it % 3;
        const uint32_t dA = bA + s * SA_BYTES;
        const uint32_t dB = bB + s * SB_BYTES;
        CP_CG16(dA + (ar0 * PA + ac0) * 2, &W[(size_t)(o0 + ar0) * C + kc + ac0]);
        if (tid < 256)
            CP_CG16(dA + (ar1 * PA + ac1) * 2, &W[(size_t)(o0 + ar1) * C + kc + ac1]);
        CP_CG16(dB + (br * PB + bc) * 2, &X[(size_t)(kc + br) * NPTS + n0 + bc]);
        CP_COMMIT();
    };

    prefetch(0);
    prefetch(1);

    float acc[3][4][4] = {};

    #pragma unroll
    for (int it = 0; it < NIT; it++) {
        if (it < NIT - 1) asm volatile("cp.async.wait_group 1;");
        else              asm volatile("cp.async.wait_group 0;");
        __syncthreads();
        if (it + 2 < NIT) prefetch(it + 2);

        const int s = it % 3;
        const uint32_t stA = bA + s * SA_BYTES;
        const uint32_t stB = bB + s * SB_BYTES;
        #pragma unroll
        for (int ks = 0; ks < 2; ks++) {
            uint32_t Bf[4][2];
            #pragma unroll
            for (int jj = 0; jj < 2; jj++) {
                uint32_t r[4];
                uint32_t off = (((lane & 15) + ks * 16) * PB +
                                warp_n + jj * 16 + (lane >> 4) * 8) * 2;
                ldsm4t(r, stB + off);
                Bf[2 * jj][0] = r[0]; Bf[2 * jj][1] = r[1];
                Bf[2 * jj + 1][0] = r[2]; Bf[2 * jj + 1][1] = r[3];
            }
            #pragma unroll
            for (int i = 0; i < 3; i++) {
                uint32_t Af[4];
                ldsm4(Af, stA + aOff + i * (16 * PA * 2) + ks * 32);
                #pragma unroll
                for (int j = 0; j < 4; j++)
                    mma_f16(acc[i][j], Af, Bf[j]);
            }
        }
    }

    #pragma unroll
    for (int i = 0; i < 3; i++) {
        int m = o0 + warp_m + i * 16 + (lane >> 2);
        float bv0 = bias[m], bv1 = bias[m + 8];
        #pragma unroll
        for (int j = 0; j < 4; j++) {
            int n = n0 + warp_n + j * 8 + (lane & 3) * 2;
            if (OHALF) {
                __half* Y = (__half*)Yall + (size_t)blockIdx.z * ybs;
                __half2 r0 = __floats2half2_rn(acc[i][j][0] + bv0, acc[i][j][1] + bv0);
                __half2 r1 = __floats2half2_rn(acc[i][j][2] + bv1, acc[i][j][3] + bv1);
                *reinterpret_cast<__half2*>(&Y[(size_t)m * NPTS + n]) = r0;
                *reinterpret_cast<__half2*>(&Y[(size_t)(m + 8) * NPTS + n]) = r1;
            } else {
                float* Y = (float*)Yall + (size_t)blockIdx.z * ybs;
                float2 r0 = {acc[i][j][0] + bv0, acc[i][j][1] + bv0};
                float2 r1 = {acc[i][j][2] + bv1, acc[i][j][3] + bv1};
                *reinterpret_cast<float2*>(&Y[(size_t)m * NPTS + n]) = r0;
                *reinterpret_cast<float2*>(&Y[(size_t)(m + 8) * NPTS + n]) = r1;
            }
        }
    }
}

// ---------------- depthwise 3x3x3 (fp16 in) -> fp16 q,k,v + ssq of rounded q/k ------
__global__ __launch_bounds__(256) void dwconv3(
    const __half* __restrict__ in, const float* __restrict__ w,
    const float* __restrict__ bias, __half* __restrict__ outh,
    float* __restrict__ ssq)
{
    int bc = blockIdx.x;
    int b  = bc / C3;
    int c  = bc % C3;
    const __half* vol = in + (size_t)bc * NPTS;
    __half* op = outh + (size_t)bc * NPTS;

    float wr[27];
    #pragma unroll
    for (int i = 0; i < 27; i++) wr[i] = w[c * 27 + i];
    float bv = bias[c];

    __shared__ float P[4][34][36];
    __shared__ float sred[8];
    int tid = threadIdx.x;
    for (int i = tid; i < 4 * 34 * 36; i += 256) ((float*)P)[i] = 0.f;
    __syncthreads();
    {
        int y = tid >> 3, x4 = (tid & 7) * 4;
        uint2 raw = *reinterpret_cast<const uint2*>(&vol[y * 32 + x4]);
        __half2 hA = *reinterpret_cast<__half2*>(&raw.x);
        __half2 hB = *reinterpret_cast<__half2*>(&raw.y);
        P[0][1 + y][1 + x4 + 0] = __half2float(hA.x);
        P[0][1 + y][1 + x4 + 1] = __half2float(hA.y);
        P[0][1 + y][1 + x4 + 2] = __half2float(hB.x);
        P[0][1 + y][1 + x4 + 3] = __half2float(hB.y);
    }
    __syncthreads();

    int tx4 = (tid & 7) * 4;
    int ty  = tid >> 3;
    float qs = 0.f;
    const bool is_qk = (c < 2 * C);

    for (int z = 0; z < SDIM; z++) {
        int nb = (z + 1) & 3;
        if (z + 1 < SDIM) {
            int y = tid >> 3, x4 = (tid & 7) * 4;
            uint2 raw = *reinterpret_cast<const uint2*>(&vol[(size_t)(z + 1) * 1024 + y * 32 + x4]);
            __half2 hA = *reinterpret_cast<__half2*>(&raw.x);
            __half2 hB = *reinterpret_cast<__half2*>(&raw.y);
            P[nb][1 + y][1 + x4 + 0] = __half2float(hA.x);
            P[nb][1 + y][1 + x4 + 1] = __half2float(hA.y);
            P[nb][1 + y][1 + x4 + 2] = __half2float(hB.x);
            P[nb][1 + y][1 + x4 + 3] = __half2float(hB.y);
        } else {
            for (int i = tid; i < 34 * 36; i += 256) ((float*)P[nb])[i] = 0.f;
        }
        __syncthreads();
        int pm = (z + 3) & 3;
        int pc = z & 3;
        float a0 = bv, a1 = bv, a2 = bv, a3 = bv;
        #pragma unroll
        for (int dz = 0; dz < 3; dz++) {
            int pi = (dz == 0) ? pm : (dz == 1) ? pc : nb;
            #pragma unroll
            for (int dy = 0; dy < 3; dy++) {
                const float* row = &P[pi][ty + dy][tx4];
                float4 rA = *reinterpret_cast<const float4*>(row);
                float2 rB = *reinterpret_cast<const float2*>(row + 4);
                float w0 = wr[dz * 9 + dy * 3 + 0];
                float w1 = wr[dz * 9 + dy * 3 + 1];
                float w2 = wr[dz * 9 + dy * 3 + 2];
                a0 += w0 * rA.x + w1 * rA.y + w2 * rA.z;
                a1 += w0 * rA.y + w1 * rA.z + w2 * rA.w;
                a2 += w0 * rA.z + w1 * rA.w + w2 * rB.x;
                a3 += w0 * rA.w + w1 * rB.x + w2 * rB.y;
            }
        }
        size_t off = (size_t)z * 1024 + ty * 32 + tx4;
        __half2 h0 = __floats2half2_rn(a0, a1);
        __half2 h1 = __floats2half2_rn(a2, a3);
        uint2 hv = {*reinterpret_cast<uint32_t*>(&h0), *reinterpret_cast<uint32_t*>(&h1)};
        *reinterpret_cast<uint2*>(&op[off]) = hv;
        if (is_qk) {
            float r0 = __half2float(h0.x), r1 = __half2float(h0.y);
            float r2 = __half2float(h1.x), r3 = __half2float(h1.y);
            qs += r0 * r0 + r1 * r1 + r2 * r2 + r3 * r3;
        }
    }

    if (is_qk) {
        #pragma unroll
        for (int o = 16; o > 0; o >>= 1) qs += __shfl_xor_sync(~0u, qs, o);
        if ((tid & 31) == 0) sred[tid >> 5] = qs;
        __syncthreads();
        if (tid < 8) {
            float v = sred[tid];
            #pragma unroll
            for (int o = 4; o > 0; o >>= 1) v += __shfl_xor_sync(0xffu, v, o);
            if (tid == 0) ssq[b * 2 * C + c] = v;
        }
    }
}

// ---------------- q @ k^T via fp16 mma.sync ----------------
#define QKC 128
#define QKP 136
#define QK_ARR (48 * QKP * 2)
#define QK_STAGE (2 * QK_ARR)
#define QK_NSPL 32
#define QK_SLAB (NPTS / QK_NSPL)     // 1024
#define QK_SMEM (2 * QK_STAGE + 48 * 49 * 4)

__global__ __launch_bounds__(256) void qk_mma(
    const __half* __restrict__ dwh, float* __restrict__ attn)
{
    extern __shared__ char smem[];
    float* sAcc = reinterpret_cast<float*>(smem + 2 * QK_STAGE);
    const int tid = threadIdx.x, wid = tid >> 5, lane = tid & 31;
    const int b = blockIdx.z, h = blockIdx.y;
    const int n0 = blockIdx.x * QK_SLAB;

    const __half* srcs[2] = {
        dwh + ((size_t)b * C3 + h * CH) * NPTS,
        dwh + ((size_t)b * C3 + C + h * CH) * NPTS
    };
    const uint32_t sbase = smem_u32(smem);

    for (int i = tid; i < 48 * 49; i += 256) sAcc[i] = 0.f;

    int la[6], lr[6], lc[6];
    #pragma unroll
    for (int q = 0; q < 6; q++) {
        int idx = tid + q * 256;
        la[q] = idx / 768;
        int rem = idx % 768;
        lr[q] = rem / 16;
        lc[q] = (rem % 16) * 8;
    }

    const int NCH = QK_SLAB / QKC;
    #pragma unroll
    for (int q = 0; q < 6; q++) {
        uint32_t dst = sbase + la[q] * QK_ARR + (lr[q] * QKP + lc[q]) * 2;
        CP_CG16(dst, srcs[la[q]] + (size_t)lr[q] * NPTS + n0 + lc[q]);
    }
    CP_COMMIT();

    float acc[3][6][4] = {};
    const int k0 = wid * 16;

    for (int ch = 0; ch < NCH; ch++) {
        if (ch + 1 < NCH) {
            uint32_t st = ((ch + 1) & 1) * QK_STAGE;
            int nb = n0 + (ch + 1) * QKC;
            #pragma unroll
            for (int q = 0; q < 6; q++) {
                uint32_t dst = sbase + st + la[q] * QK_ARR + (lr[q] * QKP + lc[q]) * 2;
                CP_CG16(dst, srcs[la[q]] + (size_t)lr[q] * NPTS + nb + lc[q]);
            }
            CP_COMMIT();
            asm volatile("cp.async.wait_group 1;");
        } else {
            asm volatile("cp.async.wait_group 0;");
        }
        __syncthreads();

        const uint32_t st = sbase + (ch & 1) * QK_STAGE;
        uint32_t Af[3][4], Bf[6][2];
        #pragma unroll
        for (int i = 0; i < 3; i++) {
            uint32_t off = ((i * 16 + (lane & 15)) * QKP + k0 + (lane >> 4) * 8) * 2;
            ldsm4(Af[i], st + off);
        }
        #pragma unroll
        for (int jj = 0; jj < 3; jj++) {
            uint32_t r[4];
            uint32_t off = ((jj * 16 + (lane & 7) + ((lane >> 4) << 3)) * QKP +
                            k0 + ((lane >> 3) & 1) * 8) * 2;
            ldsm4(r, st + QK_ARR + off);
            Bf[2 * jj][0] = r[0]; Bf[2 * jj][1] = r[1];
            Bf[2 * jj + 1][0] = r[2]; Bf[2 * jj + 1][1] = r[3];
        }
        #pragma unroll
        for (int i = 0; i < 3; i++)
            #pragma unroll
            for (int j = 0; j < 6; j++)
                mma_f16(acc[i][j], Af[i], Bf[j]);
        __syncthreads();
    }

    #pragma unroll
    for (int i = 0; i < 3; i++) {
        int m = i * 16 + (lane >> 2);
        #pragma unroll
        for (int j = 0; j < 6; j++) {
            int n = j * 8 + (lane & 3) * 2;
            atomicAdd(&sAcc[m * 49 + n],           acc[i][j][0]);
            atomicAdd(&sAcc[m * 49 + n + 1],       acc[i][j][1]);
            atomicAdd(&sAcc[(m + 8) * 49 + n],     acc[i][j][2]);
            atomicAdd(&sAcc[(m + 8) * 49 + n + 1], acc[i][j][3]);
        }
    }
    __syncthreads();
    float* dst = attn + (size_t)(b * HEADS + h) * CH * CH;
    for (int i = tid; i < CH * CH; i += 256)
        atomicAdd(&dst[i], sAcc[(i / CH) * 49 + (i % CH)]);
}

// ---------------- scale + softmax ----------------
__global__ void softmaxk(float* __restrict__ attn, const float* __restrict__ ssq,
                         const float* __restrict__ temp)
{
    int gw = blockIdx.x * (blockDim.x / 32) + (threadIdx.x >> 5);
    if (gw >= B * HEADS * CH) return;
    int lane = threadIdx.x & 31;
    int c = gw % CH, bh = gw / CH, h = bh % HEADS, b = bh / HEADS;
    float* row = attn + (size_t)gw * CH;
    float iq = 1.f / fmaxf(sqrtf(ssq[b * 2 * C + h * CH + c]), EPS);
    float t  = temp[h];
    int e0 = lane, e1 = lane + 32;
    float ik0 = 1.f / fmaxf(sqrtf(ssq[b * 2 * C + C + h * CH + e0]), EPS);
    float x0 = row[e0] * iq * ik0 * t;
    float x1 = -1e30f;
    if (e1 < CH) {
        float ik1 = 1.f / fmaxf(sqrtf(ssq[b * 2 * C + C + h * CH + e1]), EPS);
        x1 = row[e1] * iq * ik1 * t;
    }
    float m = fmaxf(x0, x1);
    #pragma unroll
    for (int o = 16; o > 0; o >>= 1) m = fmaxf(m, __shfl_xor_sync(~0u, m, o));
    float ex0 = expf(x0 - m);
    float ex1 = (e1 < CH) ? expf(x1 - m) : 0.f;
    float s = ex0 + ex1;
    #pragma unroll
    for (int o = 16; o > 0; o >>= 1) s += __shfl_xor_sync(~0u, s, o);
    float r = 1.f / s;
    row[e0] = ex0 * r;
    if (e1 < CH) row[e1] = ex1 * r;
}

// ---------------- fuse proj weights with attention ----------------
__global__ __launch_bounds__(192) void fuseW(const float* __restrict__ proj_w,
                                             const float* __restrict__ attn,
                                             __half* __restrict__ w2)
{
    int bh = blockIdx.x;
    int h = bh % HEADS, b = bh / HEADS;
    __shared__ float At[CH][CH];
    const float* am = attn + (size_t)bh * CH * CH;
    for (int i = threadIdx.x; i < CH * CH; i += 192)
        At[i / CH][i % CH] = am[i];
    __syncthreads();

    int o = threadIdx.x;
    float pr[CH];
    #pragma unroll
    for (int c = 0; c < CH; c++) pr[c] = proj_w[(size_t)o * C + h * CH + c];

    __half* dst = w2 + (size_t)b * C * C + (size_t)o * C + h * CH;
    #pragma unroll 4
    for (int e = 0; e < CH; e++) {
        float acc = 0.f;
        #pragma unroll
        for (int c = 0; c < CH; c++) acc += pr[c] * At[c][e];
        dst[e] = __float2half_rn(acc);
    }
}

// ---------------- launch ----------------
extern "C" void kernel_launch(void* const* d_in, const int* in_sizes, int n_in,
                              void* d_out, int out_size)
{
    const float* x      = (const float*)d_in[0];
    const float* qkv_w  = (const float*)d_in[1];
    const float* qkv_b  = (const float*)d_in[2];
    const float* dw_w   = (const float*)d_in[3];
    const float* dw_b   = (const float*)d_in[4];
    const float* proj_w = (const float*)d_in[5];
    const float* proj_b = (const float*)d_in[6];
    const float* temp   = (const float*)d_in[7];
    float* out = (float*)d_out;

    float *ssqp, *atp;
    __half *xhp, *qkvhp, *dwhp, *whp, *w2p;
    cudaGetSymbolAddress((void**)&xhp,   g_xh);
    cudaGetSymbolAddress((void**)&qkvhp, g_qkvh);
    cudaGetSymbolAddress((void**)&dwhp,  g_dwh);
    cudaGetSymbolAddress((void**)&ssqp,  g_ssq);
    cudaGetSymbolAddress((void**)&atp,   g_at);
    cudaGetSymbolAddress((void**)&whp,   g_wh);
    cudaGetSymbolAddress((void**)&w2p,   g_w2h);

    cudaFuncSetAttribute(qk_mma, cudaFuncAttributeMaxDynamicSharedMemorySize, QK_SMEM);
    cudaFuncSetAttribute(gemm_mma<1>, cudaFuncAttributeMaxDynamicSharedMemorySize, GM_SMEM);
    cudaFuncSetAttribute(gemm_mma<0>, cudaFuncAttributeMaxDynamicSharedMemorySize, GM_SMEM);

    // 1) weights -> fp16 + zero attn
    cvtWz<<<(C3 * C + B * HEADS * CH * CH + 255) / 256, 256>>>(qkv_w, whp, atp);
    // 2) x -> fp16
    cvtX<<<(int)((size_t)B * C * NPTS / 4 / 256), 256>>>(x, xhp);
    // 3) qkv 1x1 conv (3-stage cp.async.cg fp16 tensor core)
    gemm_mma<1><<<dim3(C3 / BMg, NPTS / BNg, B), 512, GM_SMEM>>>(
        xhp, (size_t)C * NPTS, whp, 0, qkv_b, qkvhp, (size_t)C3 * NPTS);
    // 4) depthwise 3x3x3 <- PROFILED this round
    dwconv3<<<B * C3, 256>>>(qkvhp, dw_w, dw_b, dwhp, ssqp);
    // 5) q @ k^T
    qk_mma<<<dim3(QK_NSPL, HEADS, B), 256, QK_SMEM>>>(dwhp, atp);
    // 6) scale + softmax
    softmaxk<<<(B * HEADS * CH + 7) / 8, 256>>>(atp, ssqp, temp);
    // 7) fuse proj with attention
    fuseW<<<B * HEADS, 192>>>(proj_w, atp, w2p);
    // 8) fused (proj∘attn) @ v
    gemm_mma<0><<<dim3(1, NPTS / BNg, B), 512, GM_SMEM>>>(
        dwhp + (size_t)2 * C * NPTS, (size_t)C3 * NPTS,
        w2p, (size_t)C * C, proj_b, out, (size_t)C * NPTS);
}

// round 11
// speedup vs baseline: 1.2537x; 1.0776x over previous
#include <cuda_runtime.h>
#include <cuda_fp16.h>
#include <cstdint>

#define B 2
#define C 192
#define C3 576
#define SDIM 32
#define NPTS 32768           // 32^3
#define HEADS 4
#define CH 48
#define EPS 1e-12f

// ---------------- scratch (static device allocations) ----------------
__device__ __half g_xh  [(size_t)B * C * NPTS];      // input x in fp16
__device__ __half g_qkvh[(size_t)B * C3 * NPTS];     // after 1x1 conv (fp16)
__device__ __half g_dwh [(size_t)B * C3 * NPTS];     // after dwconv: q,k,v fp16
__device__ float  g_ssq[B * 2 * C];                  // sum of squares of ROUNDED q/k
__device__ float  g_at [B * HEADS * CH * CH];        // attention logits / probs
__device__ __half g_wh [C3 * C];                     // qkv weights fp16
__device__ __half g_w2h[B * C * C];                  // fused proj∘attn weights fp16

// ================= mma.sync helpers =================
__device__ __forceinline__ uint32_t smem_u32(const void* p) {
    uint32_t a;
    asm("{ .reg .u64 t; cvta.to.shared.u64 t, %1; cvt.u32.u64 %0, t; }" : "=r"(a) : "l"(p));
    return a;
}
__device__ __forceinline__ void ldsm4(uint32_t* r, uint32_t a) {
    asm volatile("ldmatrix.sync.aligned.m8n8.x4.shared.b16 {%0,%1,%2,%3}, [%4];"
                 : "=r"(r[0]), "=r"(r[1]), "=r"(r[2]), "=r"(r[3]) : "r"(a));
}
__device__ __forceinline__ void ldsm4t(uint32_t* r, uint32_t a) {
    asm volatile("ldmatrix.sync.aligned.m8n8.x4.trans.shared.b16 {%0,%1,%2,%3}, [%4];"
                 : "=r"(r[0]), "=r"(r[1]), "=r"(r[2]), "=r"(r[3]) : "r"(a));
}
__device__ __forceinline__ void mma_f16(float* d, const uint32_t* a, const uint32_t* b) {
    asm volatile(
        "mma.sync.aligned.m16n8k16.row.col.f32.f16.f16.f32 "
        "{%0,%1,%2,%3}, {%4,%5,%6,%7}, {%8,%9}, {%0,%1,%2,%3};"
        : "+f"(d[0]), "+f"(d[1]), "+f"(d[2]), "+f"(d[3])
        : "r"(a[0]), "r"(a[1]), "r"(a[2]), "r"(a[3]), "r"(b[0]), "r"(b[1]));
}
#define CP_CG16(dst, src) \
    asm volatile("cp.async.cg.shared.global [%0], [%1], 16;" :: "r"(dst), "l"(src))
#define CP_COMMIT() asm volatile("cp.async.commit_group;")

// ---------------- setup kernels ----------------
__global__ void cvtWz(const float* __restrict__ qkv_w, __half* __restrict__ wh,
                      float* __restrict__ attn)
{
    int i = blockIdx.x * 256 + threadIdx.x;
    const int T0 = C3 * C;
    const int T1 = T0 + B * HEADS * CH * CH;
    if (i < T0)       wh[i] = __float2half_rn(qkv_w[i]);
    else if (i < T1)  attn[i - T0] = 0.f;
}
__global__ void cvtX(const float* __restrict__ x, __half* __restrict__ xh)
{
    size_t i = ((size_t)blockIdx.x * 256 + threadIdx.x) * 4;
    float4 v = *reinterpret_cast<const float4*>(&x[i]);
    __half2 h0 = __floats2half2_rn(v.x, v.y);
    __half2 h1 = __floats2half2_rn(v.z, v.w);
    uint2 r = {*reinterpret_cast<uint32_t*>(&h0), *reinterpret_cast<uint32_t*>(&h1)};
    *reinterpret_cast<uint2*>(&xh[i]) = r;
}

// ---------------- 1x1 conv GEMM via fp16 mma.sync, 3-stage cp.async.cg ------------
#define BMg 192
#define BNg 128
#define BKg 32
#define PA 40
#define PB 136
#define SA_BYTES (BMg * PA * 2)      // 15360
#define SB_BYTES (BKg * PB * 2)      // 8704
#define GM_SMEM  (3 * (SA_BYTES + SB_BYTES))   // 72192
#define NIT (C / BKg)                // 6

template<int OHALF>
__global__ __launch_bounds__(512) void gemm_mma(
    const __half* __restrict__ Xall, size_t xbs,
    const __half* __restrict__ WH, size_t wbs,
    const float* __restrict__ bias, void* __restrict__ Yall, size_t ybs)
{
    extern __shared__ char gsm[];
    const int tid = threadIdx.x, wid = tid >> 5, lane = tid & 31;
    const int o0 = blockIdx.x * BMg;
    const int n0 = blockIdx.y * BNg;
    const __half* X = Xall + (size_t)blockIdx.z * xbs;
    const __half* W = WH + (size_t)blockIdx.z * wbs;

    const int warp_m = (wid >> 2) * 48;
    const int warp_n = (wid & 3) * 32;

    const uint32_t bA = smem_u32(gsm);
    const uint32_t bB = bA + 3 * SA_BYTES;
    const uint32_t aOff = ((warp_m + (lane & 15)) * PA + (lane >> 4) * 8) * 2;

    const int ar0 = tid >> 2,          ac0 = (tid & 3) * 8;
    const int ar1 = (tid + 512) >> 2,  ac1 = ((tid + 512) & 3) * 8;
    const int br  = tid >> 4,          bc  = (tid & 15) * 8;

    auto prefetch = [&](int it) {
        const int kc = it * BKg;
        const int s  = it % 3;
        const uint32_t dA = bA + s * SA_BYTES;
        const uint32_t dB = bB + s * SB_BYTES;
        CP_CG16(dA + (ar0 * PA + ac0) * 2, &W[(size_t)(o0 + ar0) * C + kc + ac0]);
        if (tid < 256)
            CP_CG16(dA + (ar1 * PA + ac1) * 2, &W[(size_t)(o0 + ar1) * C + kc + ac1]);
        CP_CG16(dB + (br * PB + bc) * 2, &X[(size_t)(kc + br) * NPTS + n0 + bc]);
        CP_COMMIT();
    };

    prefetch(0);
    prefetch(1);

    float acc[3][4][4] = {};

    #pragma unroll
    for (int it = 0; it < NIT; it++) {
        if (it < NIT - 1) asm volatile("cp.async.wait_group 1;");
        else              asm volatile("cp.async.wait_group 0;");
        __syncthreads();
        if (it + 2 < NIT) prefetch(it + 2);

        const int s = it % 3;
        const uint32_t stA = bA + s * SA_BYTES;
        const uint32_t stB = bB + s * SB_BYTES;
        #pragma unroll
        for (int ks = 0; ks < 2; ks++) {
            uint32_t Bf[4][2];
            #pragma unroll
            for (int jj = 0; jj < 2; jj++) {
                uint32_t r[4];
                uint32_t off = (((lane & 15) + ks * 16) * PB +
                                warp_n + jj * 16 + (lane >> 4) * 8) * 2;
                ldsm4t(r, stB + off);
                Bf[2 * jj][0] = r[0]; Bf[2 * jj][1] = r[1];
                Bf[2 * jj + 1][0] = r[2]; Bf[2 * jj + 1][1] = r[3];
            }
            #pragma unroll
            for (int i = 0; i < 3; i++) {
                uint32_t Af[4];
                ldsm4(Af, stA + aOff + i * (16 * PA * 2) + ks * 32);
                #pragma unroll
                for (int j = 0; j < 4; j++)
                    mma_f16(acc[i][j], Af, Bf[j]);
            }
        }
    }

    #pragma unroll
    for (int i = 0; i < 3; i++) {
        int m = o0 + warp_m + i * 16 + (lane >> 2);
        float bv0 = bias[m], bv1 = bias[m + 8];
        #pragma unroll
        for (int j = 0; j < 4; j++) {
            int n = n0 + warp_n + j * 8 + (lane & 3) * 2;
            if (OHALF) {
                __half* Y = (__half*)Yall + (size_t)blockIdx.z * ybs;
                __half2 r0 = __floats2half2_rn(acc[i][j][0] + bv0, acc[i][j][1] + bv0);
                __half2 r1 = __floats2half2_rn(acc[i][j][2] + bv1, acc[i][j][3] + bv1);
                *reinterpret_cast<__half2*>(&Y[(size_t)m * NPTS + n]) = r0;
                *reinterpret_cast<__half2*>(&Y[(size_t)(m + 8) * NPTS + n]) = r1;
            } else {
                float* Y = (float*)Yall + (size_t)blockIdx.z * ybs;
                float2 r0 = {acc[i][j][0] + bv0, acc[i][j][1] + bv0};
                float2 r1 = {acc[i][j][2] + bv1, acc[i][j][3] + bv1};
                *reinterpret_cast<float2*>(&Y[(size_t)m * NPTS + n]) = r0;
                *reinterpret_cast<float2*>(&Y[(size_t)(m + 8) * NPTS + n]) = r1;
            }
        }
    }
}

// ---------------- depthwise 3x3x3: z-register rotation, 2-plane ring ---------------
// Plane p contributes c2->out[p-1], c1->out[p], c0->out[p+1]; each plane's smem rows
// are read ONCE (3 rows), all three dz-partials computed together.
__global__ __launch_bounds__(256) void dwconv3(
    const __half* __restrict__ in, const float* __restrict__ w,
    const float* __restrict__ bias, __half* __restrict__ outh,
    float* __restrict__ ssq)
{
    int bc = blockIdx.x;
    int b  = bc / C3;
    int c  = bc % C3;
    const __half* vol = in + (size_t)bc * NPTS;
    __half* op = outh + (size_t)bc * NPTS;

    float wr[27];
    #pragma unroll
    for (int i = 0; i < 27; i++) wr[i] = w[c * 27 + i];
    float bv = bias[c];

    __shared__ float P[2][34][36];
    __shared__ float sred[8];
    int tid = threadIdx.x;
    for (int i = tid; i < 2 * 34 * 36; i += 256) ((float*)P)[i] = 0.f;
    __syncthreads();

    const int ly = tid >> 3, lx4 = (tid & 7) * 4;
    {   // plane 0 -> slot 0
        uint2 raw = *reinterpret_cast<const uint2*>(&vol[ly * 32 + lx4]);
        __half2 hA = *reinterpret_cast<__half2*>(&raw.x);
        __half2 hB = *reinterpret_cast<__half2*>(&raw.y);
        P[0][1 + ly][1 + lx4 + 0] = __half2float(hA.x);
        P[0][1 + ly][1 + lx4 + 1] = __half2float(hA.y);
        P[0][1 + ly][1 + lx4 + 2] = __half2float(hB.x);
        P[0][1 + ly][1 + lx4 + 3] = __half2float(hB.y);
    }
    __syncthreads();

    float qs = 0.f;
    const bool is_qk = (c < 2 * C);

    float a0[4], a1[4];                  // carried accumulators: out[z], out[z+1]
    #pragma unroll
    for (int i = 0; i < 4; i++) { a0[i] = bv; a1[i] = bv; }

    for (int z = 0; z < SDIM; z++) {
        // issue next-plane LDG early (latency overlaps compute)
        uint2 raw;
        if (z + 1 < SDIM)
            raw = *reinterpret_cast<const uint2*>(&vol[(size_t)(z + 1) * 1024 + ly * 32 + lx4]);

        // 2D partials of plane z for the three dz roles
        float cd[3][4] = {};
        const int s = z & 1;
        #pragma unroll
        for (int dy = 0; dy < 3; dy++) {
            const float* row = &P[s][ly + dy][lx4];
            float4 rA = *reinterpret_cast<const float4*>(row);
            float2 rB = *reinterpret_cast<const float2*>(row + 4);
            #pragma unroll
            for (int dz = 0; dz < 3; dz++) {
                float w0 = wr[dz * 9 + dy * 3 + 0];
                float w1 = wr[dz * 9 + dy * 3 + 1];
                float w2 = wr[dz * 9 + dy * 3 + 2];
                cd[dz][0] += w0 * rA.x + w1 * rA.y + w2 * rA.z;
                cd[dz][1] += w0 * rA.y + w1 * rA.z + w2 * rA.w;
                cd[dz][2] += w0 * rA.z + w1 * rA.w + w2 * rB.x;
                cd[dz][3] += w0 * rA.w + w1 * rB.x + w2 * rB.y;
            }
        }

        if (z > 0) {   // out[z-1] completes with plane z's dz=2 partial
            float o0 = a0[0] + cd[2][0], o1 = a0[1] + cd[2][1];
            float o2 = a0[2] + cd[2][2], o3 = a0[3] + cd[2][3];
            __half2 h0 = __floats2half2_rn(o0, o1);
            __half2 h1 = __floats2half2_rn(o2, o3);
            uint2 hv = {*reinterpret_cast<uint32_t*>(&h0), *reinterpret_cast<uint32_t*>(&h1)};
            *reinterpret_cast<uint2*>(&op[(size_t)(z - 1) * 1024 + ly * 32 + lx4]) = hv;
            if (is_qk) {
                float r0 = __half2float(h0.x), r1 = __half2float(h0.y);
                float r2 = __half2float(h1.x), r3 = __half2float(h1.y);
                qs += r0 * r0 + r1 * r1 + r2 * r2 + r3 * r3;
            }
        }
        // rotate: a0 <- a1 + c1(plane z), a1 <- bv + c0(plane z)
        #pragma unroll
        for (int i = 0; i < 4; i++) {
            a0[i] = a1[i] + cd[1][i];
            a1[i] = bv + cd[0][i];
        }

        // stage next plane into the other slot, then sync (protects next iter's reads
        // AND this slot's reuse at z+2)
        if (z + 1 < SDIM) {
            __half2 hA = *reinterpret_cast<__half2*>(&raw.x);
            __half2 hB = *reinterpret_cast<__half2*>(&raw.y);
            P[s ^ 1][1 + ly][1 + lx4 + 0] = __half2float(hA.x);
            P[s ^ 1][1 + ly][1 + lx4 + 1] = __half2float(hA.y);
            P[s ^ 1][1 + ly][1 + lx4 + 2] = __half2float(hB.x);
            P[s ^ 1][1 + ly][1 + lx4 + 3] = __half2float(hB.y);
        }
        __syncthreads();
    }
    {   // out[31]: dz=2 contribution is zero padding
        __half2 h0 = __floats2half2_rn(a0[0], a0[1]);
        __half2 h1 = __floats2half2_rn(a0[2], a0[3]);
        uint2 hv = {*reinterpret_cast<uint32_t*>(&h0), *reinterpret_cast<uint32_t*>(&h1)};
        *reinterpret_cast<uint2*>(&op[(size_t)31 * 1024 + ly * 32 + lx4]) = hv;
        if (is_qk) {
            float r0 = __half2float(h0.x), r1 = __half2float(h0.y);
            float r2 = __half2float(h1.x), r3 = __half2float(h1.y);
            qs += r0 * r0 + r1 * r1 + r2 * r2 + r3 * r3;
        }
    }

    if (is_qk) {
        #pragma unroll
        for (int o = 16; o > 0; o >>= 1) qs += __shfl_xor_sync(~0u, qs, o);
        if ((tid & 31) == 0) sred[tid >> 5] = qs;
        __syncthreads();
        if (tid < 8) {
            float v = sred[tid];
            #pragma unroll
            for (int o = 4; o > 0; o >>= 1) v += __shfl_xor_sync(0xffu, v, o);
            if (tid == 0) ssq[b * 2 * C + c] = v;
        }
    }
}

// ---------------- q @ k^T via fp16 mma.sync ----------------
#define QKC 128
#define QKP 136
#define QK_ARR (48 * QKP * 2)
#define QK_STAGE (2 * QK_ARR)
#define QK_NSPL 32
#define QK_SLAB (NPTS / QK_NSPL)     // 1024
#define QK_SMEM (2 * QK_STAGE + 48 * 49 * 4)

__global__ __launch_bounds__(256) void qk_mma(
    const __half* __restrict__ dwh, float* __restrict__ attn)
{
    extern __shared__ char smem[];
    float* sAcc = reinterpret_cast<float*>(smem + 2 * QK_STAGE);
    const int tid = threadIdx.x, wid = tid >> 5, lane = tid & 31;
    const int b = blockIdx.z, h = blockIdx.y;
    const int n0 = blockIdx.x * QK_SLAB;

    const __half* srcs[2] = {
        dwh + ((size_t)b * C3 + h * CH) * NPTS,
        dwh + ((size_t)b * C3 + C + h * CH) * NPTS
    };
    const uint32_t sbase = smem_u32(smem);

    for (int i = tid; i < 48 * 49; i += 256) sAcc[i] = 0.f;

    int la[6], lr[6], lc[6];
    #pragma unroll
    for (int q = 0; q < 6; q++) {
        int idx = tid + q * 256;
        la[q] = idx / 768;
        int rem = idx % 768;
        lr[q] = rem / 16;
        lc[q] = (rem % 16) * 8;
    }

    const int NCH = QK_SLAB / QKC;
    #pragma unroll
    for (int q = 0; q < 6; q++) {
        uint32_t dst = sbase + la[q] * QK_ARR + (lr[q] * QKP + lc[q]) * 2;
        CP_CG16(dst, srcs[la[q]] + (size_t)lr[q] * NPTS + n0 + lc[q]);
    }
    CP_COMMIT();

    float acc[3][6][4] = {};
    const int k0 = wid * 16;

    for (int ch = 0; ch < NCH; ch++) {
        if (ch + 1 < NCH) {
            uint32_t st = ((ch + 1) & 1) * QK_STAGE;
            int nb = n0 + (ch + 1) * QKC;
            #pragma unroll
            for (int q = 0; q < 6; q++) {
                uint32_t dst = sbase + st + la[q] * QK_ARR + (lr[q] * QKP + lc[q]) * 2;
                CP_CG16(dst, srcs[la[q]] + (size_t)lr[q] * NPTS + nb + lc[q]);
            }
            CP_COMMIT();
            asm volatile("cp.async.wait_group 1;");
        } else {
            asm volatile("cp.async.wait_group 0;");
        }
        __syncthreads();

        const uint32_t st = sbase + (ch & 1) * QK_STAGE;
        uint32_t Af[3][4], Bf[6][2];
        #pragma unroll
        for (int i = 0; i < 3; i++) {
            uint32_t off = ((i * 16 + (lane & 15)) * QKP + k0 + (lane >> 4) * 8) * 2;
            ldsm4(Af[i], st + off);
        }
        #pragma unroll
        for (int jj = 0; jj < 3; jj++) {
            uint32_t r[4];
            uint32_t off = ((jj * 16 + (lane & 7) + ((lane >> 4) << 3)) * QKP +
                            k0 + ((lane >> 3) & 1) * 8) * 2;
            ldsm4(r, st + QK_ARR + off);
            Bf[2 * jj][0] = r[0]; Bf[2 * jj][1] = r[1];
            Bf[2 * jj + 1][0] = r[2]; Bf[2 * jj + 1][1] = r[3];
        }
        #pragma unroll
        for (int i = 0; i < 3; i++)
            #pragma unroll
            for (int j = 0; j < 6; j++)
                mma_f16(acc[i][j], Af[i], Bf[j]);
        __syncthreads();
    }

    #pragma unroll
    for (int i = 0; i < 3; i++) {
        int m = i * 16 + (lane >> 2);
        #pragma unroll
        for (int j = 0; j < 6; j++) {
            int n = j * 8 + (lane & 3) * 2;
            atomicAdd(&sAcc[m * 49 + n],           acc[i][j][0]);
            atomicAdd(&sAcc[m * 49 + n + 1],       acc[i][j][1]);
            atomicAdd(&sAcc[(m + 8) * 49 + n],     acc[i][j][2]);
            atomicAdd(&sAcc[(m + 8) * 49 + n + 1], acc[i][j][3]);
        }
    }
    __syncthreads();
    float* dst = attn + (size_t)(b * HEADS + h) * CH * CH;
    for (int i = tid; i < CH * CH; i += 256)
        atomicAdd(&dst[i], sAcc[(i / CH) * 49 + (i % CH)]);
}

// ---------------- scale + softmax ----------------
__global__ void softmaxk(float* __restrict__ attn, const float* __restrict__ ssq,
                         const float* __restrict__ temp)
{
    int gw = blockIdx.x * (blockDim.x / 32) + (threadIdx.x >> 5);
    if (gw >= B * HEADS * CH) return;
    int lane = threadIdx.x & 31;
    int c = gw % CH, bh = gw / CH, h = bh % HEADS, b = bh / HEADS;
    float* row = attn + (size_t)gw * CH;
    float iq = 1.f / fmaxf(sqrtf(ssq[b * 2 * C + h * CH + c]), EPS);
    float t  = temp[h];
    int e0 = lane, e1 = lane + 32;
    float ik0 = 1.f / fmaxf(sqrtf(ssq[b * 2 * C + C + h * CH + e0]), EPS);
    float x0 = row[e0] * iq * ik0 * t;
    float x1 = -1e30f;
    if (e1 < CH) {
        float ik1 = 1.f / fmaxf(sqrtf(ssq[b * 2 * C + C + h * CH + e1]), EPS);
        x1 = row[e1] * iq * ik1 * t;
    }
    float m = fmaxf(x0, x1);
    #pragma unroll
    for (int o = 16; o > 0; o >>= 1) m = fmaxf(m, __shfl_xor_sync(~0u, m, o));
    float ex0 = expf(x0 - m);
    float ex1 = (e1 < CH) ? expf(x1 - m) : 0.f;
    float s = ex0 + ex1;
    #pragma unroll
    for (int o = 16; o > 0; o >>= 1) s += __shfl_xor_sync(~0u, s, o);
    float r = 1.f / s;
    row[e0] = ex0 * r;
    if (e1 < CH) row[e1] = ex1 * r;
}

// ---------------- fuse proj weights with attention ----------------
__global__ __launch_bounds__(192) void fuseW(const float* __restrict__ proj_w,
                                             const float* __restrict__ attn,
                                             __half* __restrict__ w2)
{
    int bh = blockIdx.x;
    int h = bh % HEADS, b = bh / HEADS;
    __shared__ float At[CH][CH];
    const float* am = attn + (size_t)bh * CH * CH;
    for (int i = threadIdx.x; i < CH * CH; i += 192)
        At[i / CH][i % CH] = am[i];
    __syncthreads();

    int o = threadIdx.x;
    float pr[CH];
    #pragma unroll
    for (int c = 0; c < CH; c++) pr[c] = proj_w[(size_t)o * C + h * CH + c];

    __half* dst = w2 + (size_t)b * C * C + (size_t)o * C + h * CH;
    #pragma unroll 4
    for (int e = 0; e < CH; e++) {
        float acc = 0.f;
        #pragma unroll
        for (int c = 0; c < CH; c++) acc += pr[c] * At[c][e];
        dst[e] = __float2half_rn(acc);
    }
}

// ---------------- launch ----------------
extern "C" void kernel_launch(void* const* d_in, const int* in_sizes, int n_in,
                              void* d_out, int out_size)
{
    const float* x      = (const float*)d_in[0];
    const float* qkv_w  = (const float*)d_in[1];
    const float* qkv_b  = (const float*)d_in[2];
    const float* dw_w   = (const float*)d_in[3];
    const float* dw_b   = (const float*)d_in[4];
    const float* proj_w = (const float*)d_in[5];
    const float* proj_b = (const float*)d_in[6];
    const float* temp   = (const float*)d_in[7];
    float* out = (float*)d_out;

    float *ssqp, *atp;
    __half *xhp, *qkvhp, *dwhp, *whp, *w2p;
    cudaGetSymbolAddress((void**)&xhp,   g_xh);
    cudaGetSymbolAddress((void**)&qkvhp, g_qkvh);
    cudaGetSymbolAddress((void**)&dwhp,  g_dwh);
    cudaGetSymbolAddress((void**)&ssqp,  g_ssq);
    cudaGetSymbolAddress((void**)&atp,   g_at);
    cudaGetSymbolAddress((void**)&whp,   g_wh);
    cudaGetSymbolAddress((void**)&w2p,   g_w2h);

    cudaFuncSetAttribute(qk_mma, cudaFuncAttributeMaxDynamicSharedMemorySize, QK_SMEM);
    cudaFuncSetAttribute(gemm_mma<1>, cudaFuncAttributeMaxDynamicSharedMemorySize, GM_SMEM);
    cudaFuncSetAttribute(gemm_mma<0>, cudaFuncAttributeMaxDynamicSharedMemorySize, GM_SMEM);

    // 1) weights -> fp16 + zero attn
    cvtWz<<<(C3 * C + B * HEADS * CH * CH + 255) / 256, 256>>>(qkv_w, whp, atp);
    // 2) x -> fp16
    cvtX<<<(int)((size_t)B * C * NPTS / 4 / 256), 256>>>(x, xhp);
    // 3) qkv 1x1 conv
    gemm_mma<1><<<dim3(C3 / BMg, NPTS / BNg, B), 512, GM_SMEM>>>(
        xhp, (size_t)C * NPTS, whp, 0, qkv_b, qkvhp, (size_t)C3 * NPTS);
    // 4) depthwise 3x3x3 (z-register rotation) <- PROFILED
    dwconv3<<<B * C3, 256>>>(qkvhp, dw_w, dw_b, dwhp, ssqp);
    // 5) q @ k^T
    qk_mma<<<dim3(QK_NSPL, HEADS, B), 256, QK_SMEM>>>(dwhp, atp);
    // 6) scale + softmax
    softmaxk<<<(B * HEADS * CH + 7) / 8, 256>>>(atp, ssqp, temp);
    // 7) fuse proj with attention
    fuseW<<<B * HEADS, 192>>>(proj_w, atp, w2p);
    // 8) fused (proj∘attn) @ v
    gemm_mma<0><<<dim3(1, NPTS / BNg, B), 512, GM_SMEM>>>(
        dwhp + (size_t)2 * C * NPTS, (size_t)C3 * NPTS,
        w2p, (size_t)C * C, proj_b, out, (size_t)C * NPTS);
}

// round 12
// speedup vs baseline: 1.3501x; 1.0769x over previous
#include <cuda_runtime.h>
#include <cuda_fp16.h>
#include <cstdint>

#define B 2
#define C 192
#define C3 576
#define SDIM 32
#define NPTS 32768           // 32^3
#define HEADS 4
#define CH 48
#define EPS 1e-12f

// ---------------- scratch (static device allocations) ----------------
__device__ __half g_xh  [(size_t)B * C * NPTS];      // input x in fp16
__device__ __half g_qkvh[(size_t)B * C3 * NPTS];     // after 1x1 conv (fp16)
__device__ __half g_dwh [(size_t)B * C3 * NPTS];     // after dwconv: q,k,v fp16
__device__ float  g_ssq[B * 2 * C];                  // sum of squares of ROUNDED q/k
__device__ float  g_at [B * HEADS * CH * CH];        // attention logits / probs
__device__ __half g_wh [C3 * C];                     // qkv weights fp16
__device__ __half g_w2h[B * C * C];                  // fused proj∘attn weights fp16

// ================= mma.sync helpers =================
__device__ __forceinline__ uint32_t smem_u32(const void* p) {
    uint32_t a;
    asm("{ .reg .u64 t; cvta.to.shared.u64 t, %1; cvt.u32.u64 %0, t; }" : "=r"(a) : "l"(p));
    return a;
}
__device__ __forceinline__ void ldsm4(uint32_t* r, uint32_t a) {
    asm volatile("ldmatrix.sync.aligned.m8n8.x4.shared.b16 {%0,%1,%2,%3}, [%4];"
                 : "=r"(r[0]), "=r"(r[1]), "=r"(r[2]), "=r"(r[3]) : "r"(a));
}
__device__ __forceinline__ void ldsm4t(uint32_t* r, uint32_t a) {
    asm volatile("ldmatrix.sync.aligned.m8n8.x4.trans.shared.b16 {%0,%1,%2,%3}, [%4];"
                 : "=r"(r[0]), "=r"(r[1]), "=r"(r[2]), "=r"(r[3]) : "r"(a));
}
__device__ __forceinline__ void mma_f16(float* d, const uint32_t* a, const uint32_t* b) {
    asm volatile(
        "mma.sync.aligned.m16n8k16.row.col.f32.f16.f16.f32 "
        "{%0,%1,%2,%3}, {%4,%5,%6,%7}, {%8,%9}, {%0,%1,%2,%3};"
        : "+f"(d[0]), "+f"(d[1]), "+f"(d[2]), "+f"(d[3])
        : "r"(a[0]), "r"(a[1]), "r"(a[2]), "r"(a[3]), "r"(b[0]), "r"(b[1]));
}
#define CP_CG16(dst, src) \
    asm volatile("cp.async.cg.shared.global [%0], [%1], 16;" :: "r"(dst), "l"(src))
#define CP_COMMIT() asm volatile("cp.async.commit_group;")

// ================= packed fp32x2 helpers (sm_100+ family) =================
typedef unsigned long long u64t;
__device__ __forceinline__ u64t pk2(float lo, float hi) {
    u64t d;
    asm("mov.b64 %0, {%1, %2};" : "=l"(d) : "f"(lo), "f"(hi));
    return d;
}
__device__ __forceinline__ void upk2(u64t d, float& lo, float& hi) {
    asm("mov.b64 {%0, %1}, %2;" : "=f"(lo), "=f"(hi) : "l"(d));
}
__device__ __forceinline__ void fma2(u64t& a, u64t x, u64t y) {
    asm("fma.rn.f32x2 %0, %1, %2, %0;" : "+l"(a) : "l"(x), "l"(y));
}
__device__ __forceinline__ u64t add2(u64t x, u64t y) {
    u64t d;
    asm("add.rn.f32x2 %0, %1, %2;" : "=l"(d) : "l"(x), "l"(y));
    return d;
}

// ---------------- setup kernels ----------------
__global__ void cvtWz(const float* __restrict__ qkv_w, __half* __restrict__ wh,
                      float* __restrict__ attn)
{
    int i = blockIdx.x * 256 + threadIdx.x;
    const int T0 = C3 * C;
    const int T1 = T0 + B * HEADS * CH * CH;
    if (i < T0)       wh[i] = __float2half_rn(qkv_w[i]);
    else if (i < T1)  attn[i - T0] = 0.f;
}
__global__ void cvtX(const float* __restrict__ x, __half* __restrict__ xh)
{
    size_t i = ((size_t)blockIdx.x * 256 + threadIdx.x) * 4;
    float4 v = *reinterpret_cast<const float4*>(&x[i]);
    __half2 h0 = __floats2half2_rn(v.x, v.y);
    __half2 h1 = __floats2half2_rn(v.z, v.w);
    uint2 r = {*reinterpret_cast<uint32_t*>(&h0), *reinterpret_cast<uint32_t*>(&h1)};
    *reinterpret_cast<uint2*>(&xh[i]) = r;
}

// ---------------- 1x1 conv GEMM via fp16 mma.sync, 3-stage cp.async.cg ------------
#define BMg 192
#define BNg 128
#define BKg 32
#define PA 40
#define PB 136
#define SA_BYTES (BMg * PA * 2)      // 15360
#define SB_BYTES (BKg * PB * 2)      // 8704
#define GM_SMEM  (3 * (SA_BYTES + SB_BYTES))   // 72192
#define NIT (C / BKg)                // 6

template<int OHALF>
__global__ __launch_bounds__(512) void gemm_mma(
    const __half* __restrict__ Xall, size_t xbs,
    const __half* __restrict__ WH, size_t wbs,
    const float* __restrict__ bias, void* __restrict__ Yall, size_t ybs)
{
    extern __shared__ char gsm[];
    const int tid = threadIdx.x, wid = tid >> 5, lane = tid & 31;
    const int o0 = blockIdx.x * BMg;
    const int n0 = blockIdx.y * BNg;
    const __half* X = Xall + (size_t)blockIdx.z * xbs;
    const __half* W = WH + (size_t)blockIdx.z * wbs;

    const int warp_m = (wid >> 2) * 48;
    const int warp_n = (wid & 3) * 32;

    const uint32_t bA = smem_u32(gsm);
    const uint32_t bB = bA + 3 * SA_BYTES;
    const uint32_t aOff = ((warp_m + (lane & 15)) * PA + (lane >> 4) * 8) * 2;

    const int ar0 = tid >> 2,          ac0 = (tid & 3) * 8;
    const int ar1 = (tid + 512) >> 2,  ac1 = ((tid + 512) & 3) * 8;
    const int br  = tid >> 4,          bc  = (tid & 15) * 8;

    auto prefetch = [&](int it) {
        const int kc = it * BKg;
        const int s  = it % 3;
        const uint32_t dA = bA + s * SA_BYTES;
        const uint32_t dB = bB + s * SB_BYTES;
        CP_CG16(dA + (ar0 * PA + ac0) * 2, &W[(size_t)(o0 + ar0) * C + kc + ac0]);
        if (tid < 256)
            CP_CG16(dA + (ar1 * PA + ac1) * 2, &W[(size_t)(o0 + ar1) * C + kc + ac1]);
        CP_CG16(dB + (br * PB + bc) * 2, &X[(size_t)(kc + br) * NPTS + n0 + bc]);
        CP_COMMIT();
    };

    prefetch(0);
    prefetch(1);

    float acc[3][4][4] = {};

    #pragma unroll
    for (int it = 0; it < NIT; it++) {
        if (it < NIT - 1) asm volatile("cp.async.wait_group 1;");
        else              asm volatile("cp.async.wait_group 0;");
        __syncthreads();
        if (it + 2 < NIT) prefetch(it + 2);

        const int s = it % 3;
        const uint32_t stA = bA + s * SA_BYTES;
        const uint32_t stB = bB + s * SB_BYTES;
        #pragma unroll
        for (int ks = 0; ks < 2; ks++) {
            uint32_t Bf[4][2];
            #pragma unroll
            for (int jj = 0; jj < 2; jj++) {
                uint32_t r[4];
                uint32_t off = (((lane & 15) + ks * 16) * PB +
                                warp_n + jj * 16 + (lane >> 4) * 8) * 2;
                ldsm4t(r, stB + off);
                Bf[2 * jj][0] = r[0]; Bf[2 * jj][1] = r[1];
                Bf[2 * jj + 1][0] = r[2]; Bf[2 * jj + 1][1] = r[3];
            }
            #pragma unroll
            for (int i = 0; i < 3; i++) {
                uint32_t Af[4];
                ldsm4(Af, stA + aOff + i * (16 * PA * 2) + ks * 32);
                #pragma unroll
                for (int j = 0; j < 4; j++)
                    mma_f16(acc[i][j], Af, Bf[j]);
            }
        }
    }

    #pragma unroll
    for (int i = 0; i < 3; i++) {
        int m = o0 + warp_m + i * 16 + (lane >> 2);
        float bv0 = bias[m], bv1 = bias[m + 8];
        #pragma unroll
        for (int j = 0; j < 4; j++) {
            int n = n0 + warp_n + j * 8 + (lane & 3) * 2;
            if (OHALF) {
                __half* Y = (__half*)Yall + (size_t)blockIdx.z * ybs;
                __half2 r0 = __floats2half2_rn(acc[i][j][0] + bv0, acc[i][j][1] + bv0);
                __half2 r1 = __floats2half2_rn(acc[i][j][2] + bv1, acc[i][j][3] + bv1);
                *reinterpret_cast<__half2*>(&Y[(size_t)m * NPTS + n]) = r0;
                *reinterpret_cast<__half2*>(&Y[(size_t)(m + 8) * NPTS + n]) = r1;
            } else {
                float* Y = (float*)Yall + (size_t)blockIdx.z * ybs;
                float2 r0 = {acc[i][j][0] + bv0, acc[i][j][1] + bv0};
                float2 r1 = {acc[i][j][2] + bv1, acc[i][j][3] + bv1};
                *reinterpret_cast<float2*>(&Y[(size_t)m * NPTS + n]) = r0;
                *reinterpret_cast<float2*>(&Y[(size_t)(m + 8) * NPTS + n]) = r1;
            }
        }
    }
}

// ---------------- depthwise 3x3x3: z-rotation + packed fp32x2 FMA ------------------
__global__ __launch_bounds__(256) void dwconv3(
    const __half* __restrict__ in, const float* __restrict__ w,
    const float* __restrict__ bias, __half* __restrict__ outh,
    float* __restrict__ ssq)
{
    int bc = blockIdx.x;
    int b  = bc / C3;
    int c  = bc % C3;
    const __half* vol = in + (size_t)bc * NPTS;
    __half* op = outh + (size_t)bc * NPTS;

    u64t ww[27];                         // packed (w,w) pairs
    #pragma unroll
    for (int i = 0; i < 27; i++) { float wv = w[c * 27 + i]; ww[i] = pk2(wv, wv); }
    float bv = bias[c];
    const u64t bb = pk2(bv, bv);

    __shared__ float P[2][34][36];
    __shared__ float sred[8];
    int tid = threadIdx.x;
    for (int i = tid; i < 2 * 34 * 36; i += 256) ((float*)P)[i] = 0.f;
    __syncthreads();

    const int ly = tid >> 3, lx4 = (tid & 7) * 4;
    {   // plane 0 -> slot 0
        uint2 raw = *reinterpret_cast<const uint2*>(&vol[ly * 32 + lx4]);
        __half2 hA = *reinterpret_cast<__half2*>(&raw.x);
        __half2 hB = *reinterpret_cast<__half2*>(&raw.y);
        P[0][1 + ly][1 + lx4 + 0] = __half2float(hA.x);
        P[0][1 + ly][1 + lx4 + 1] = __half2float(hA.y);
        P[0][1 + ly][1 + lx4 + 2] = __half2float(hB.x);
        P[0][1 + ly][1 + lx4 + 3] = __half2float(hB.y);
    }
    __syncthreads();

    float qs = 0.f;
    const bool is_qk = (c < 2 * C);

    u64t a0L = bb, a0H = bb, a1L = bb, a1H = bb;   // carried out[z], out[z+1]

    for (int z = 0; z < SDIM; z++) {
        uint2 raw;
        if (z + 1 < SDIM)
            raw = *reinterpret_cast<const uint2*>(&vol[(size_t)(z + 1) * 1024 + ly * 32 + lx4]);

        u64t cdL[3] = {0, 0, 0}, cdH[3] = {0, 0, 0};
        const int s = z & 1;
        #pragma unroll
        for (int dy = 0; dy < 3; dy++) {
            const float* row = &P[s][ly + dy][lx4];
            float4 rA = *reinterpret_cast<const float4*>(row);
            float2 rB = *reinterpret_cast<const float2*>(row + 4);
            u64t p0 = pk2(rA.x, rA.y), p1 = pk2(rA.y, rA.z), p2 = pk2(rA.z, rA.w);
            u64t p3 = pk2(rA.w, rB.x), p4 = pk2(rB.x, rB.y);
            #pragma unroll
            for (int dz = 0; dz < 3; dz++) {
                const int base = dz * 9 + dy * 3;
                fma2(cdL[dz], ww[base + 0], p0);
                fma2(cdL[dz], ww[base + 1], p1);
                fma2(cdL[dz], ww[base + 2], p2);
                fma2(cdH[dz], ww[base + 0], p2);
                fma2(cdH[dz], ww[base + 1], p3);
                fma2(cdH[dz], ww[base + 2], p4);
            }
        }

        if (z > 0) {   // out[z-1] completes with plane z's dz=2 partial
            u64t oL = add2(a0L, cdL[2]);
            u64t oH = add2(a0H, cdH[2]);
            float o0, o1, o2, o3;
            upk2(oL, o0, o1); upk2(oH, o2, o3);
            __half2 h0 = __floats2half2_rn(o0, o1);
            __half2 h1 = __floats2half2_rn(o2, o3);
            uint2 hv = {*reinterpret_cast<uint32_t*>(&h0), *reinterpret_cast<uint32_t*>(&h1)};
            *reinterpret_cast<uint2*>(&op[(size_t)(z - 1) * 1024 + ly * 32 + lx4]) = hv;
            if (is_qk) {
                float r0 = __half2float(h0.x), r1 = __half2float(h0.y);
                float r2 = __half2float(h1.x), r3 = __half2float(h1.y);
                qs += r0 * r0 + r1 * r1 + r2 * r2 + r3 * r3;
            }
        }
        a0L = add2(a1L, cdL[1]); a0H = add2(a1H, cdH[1]);
        a1L = add2(bb, cdL[0]);  a1H = add2(bb, cdH[0]);

        if (z + 1 < SDIM) {
            __half2 hA = *reinterpret_cast<__half2*>(&raw.x);
            __half2 hB = *reinterpret_cast<__half2*>(&raw.y);
            P[s ^ 1][1 + ly][1 + lx4 + 0] = __half2float(hA.x);
            P[s ^ 1][1 + ly][1 + lx4 + 1] = __half2float(hA.y);
            P[s ^ 1][1 + ly][1 + lx4 + 2] = __half2float(hB.x);
            P[s ^ 1][1 + ly][1 + lx4 + 3] = __half2float(hB.y);
        }
        __syncthreads();
    }
    {   // out[31]: dz=2 contribution is zero padding
        float o0, o1, o2, o3;
        upk2(a0L, o0, o1); upk2(a0H, o2, o3);
        __half2 h0 = __floats2half2_rn(o0, o1);
        __half2 h1 = __floats2half2_rn(o2, o3);
        uint2 hv = {*reinterpret_cast<uint32_t*>(&h0), *reinterpret_cast<uint32_t*>(&h1)};
        *reinterpret_cast<uint2*>(&op[(size_t)31 * 1024 + ly * 32 + lx4]) = hv;
        if (is_qk) {
            float r0 = __half2float(h0.x), r1 = __half2float(h0.y);
            float r2 = __half2float(h1.x), r3 = __half2float(h1.y);
            qs += r0 * r0 + r1 * r1 + r2 * r2 + r3 * r3;
        }
    }

    if (is_qk) {
        #pragma unroll
        for (int o = 16; o > 0; o >>= 1) qs += __shfl_xor_sync(~0u, qs, o);
        if ((tid & 31) == 0) sred[tid >> 5] = qs;
        __syncthreads();
        if (tid < 8) {
            float v = sred[tid];
            #pragma unroll
            for (int o = 4; o > 0; o >>= 1) v += __shfl_xor_sync(0xffu, v, o);
            if (tid == 0) ssq[b * 2 * C + c] = v;
        }
    }
}

// ---------------- q @ k^T via fp16 mma.sync ----------------
#define QKC 128
#define QKP 136
#define QK_ARR (48 * QKP * 2)
#define QK_STAGE (2 * QK_ARR)
#define QK_NSPL 32
#define QK_SLAB (NPTS / QK_NSPL)     // 1024
#define QK_SMEM (2 * QK_STAGE + 48 * 49 * 4)

__global__ __launch_bounds__(256) void qk_mma(
    const __half* __restrict__ dwh, float* __restrict__ attn)
{
    extern __shared__ char smem[];
    float* sAcc = reinterpret_cast<float*>(smem + 2 * QK_STAGE);
    const int tid = threadIdx.x, wid = tid >> 5, lane = tid & 31;
    const int b = blockIdx.z, h = blockIdx.y;
    const int n0 = blockIdx.x * QK_SLAB;

    const __half* srcs[2] = {
        dwh + ((size_t)b * C3 + h * CH) * NPTS,
        dwh + ((size_t)b * C3 + C + h * CH) * NPTS
    };
    const uint32_t sbase = smem_u32(smem);

    for (int i = tid; i < 48 * 49; i += 256) sAcc[i] = 0.f;

    int la[6], lr[6], lc[6];
    #pragma unroll
    for (int q = 0; q < 6; q++) {
        int idx = tid + q * 256;
        la[q] = idx / 768;
        int rem = idx % 768;
        lr[q] = rem / 16;
        lc[q] = (rem % 16) * 8;
    }

    const int NCH = QK_SLAB / QKC;
    #pragma unroll
    for (int q = 0; q < 6; q++) {
        uint32_t dst = sbase + la[q] * QK_ARR + (lr[q] * QKP + lc[q]) * 2;
        CP_CG16(dst, srcs[la[q]] + (size_t)lr[q] * NPTS + n0 + lc[q]);
    }
    CP_COMMIT();

    float acc[3][6][4] = {};
    const int k0 = wid * 16;

    for (int ch = 0; ch < NCH; ch++) {
        if (ch + 1 < NCH) {
            uint32_t st = ((ch + 1) & 1) * QK_STAGE;
            int nb = n0 + (ch + 1) * QKC;
            #pragma unroll
            for (int q = 0; q < 6; q++) {
                uint32_t dst = sbase + st + la[q] * QK_ARR + (lr[q] * QKP + lc[q]) * 2;
                CP_CG16(dst, srcs[la[q]] + (size_t)lr[q] * NPTS + nb + lc[q]);
            }
            CP_COMMIT();
            asm volatile("cp.async.wait_group 1;");
        } else {
            asm volatile("cp.async.wait_group 0;");
        }
        __syncthreads();

        const uint32_t st = sbase + (ch & 1) * QK_STAGE;
        uint32_t Af[3][4], Bf[6][2];
        #pragma unroll
        for (int i = 0; i < 3; i++) {
            uint32_t off = ((i * 16 + (lane & 15)) * QKP + k0 + (lane >> 4) * 8) * 2;
            ldsm4(Af[i], st + off);
        }
        #pragma unroll
        for (int jj = 0; jj < 3; jj++) {
            uint32_t r[4];
            uint32_t off = ((jj * 16 + (lane & 7) + ((lane >> 4) << 3)) * QKP +
                            k0 + ((lane >> 3) & 1) * 8) * 2;
            ldsm4(r, st + QK_ARR + off);
            Bf[2 * jj][0] = r[0]; Bf[2 * jj][1] = r[1];
            Bf[2 * jj + 1][0] = r[2]; Bf[2 * jj + 1][1] = r[3];
        }
        #pragma unroll
        for (int i = 0; i < 3; i++)
            #pragma unroll
            for (int j = 0; j < 6; j++)
                mma_f16(acc[i][j], Af[i], Bf[j]);
        __syncthreads();
    }

    #pragma unroll
    for (int i = 0; i < 3; i++) {
        int m = i * 16 + (lane >> 2);
        #pragma unroll
        for (int j = 0; j < 6; j++) {
            int n = j * 8 + (lane & 3) * 2;
            atomicAdd(&sAcc[m * 49 + n],           acc[i][j][0]);
            atomicAdd(&sAcc[m * 49 + n + 1],       acc[i][j][1]);
            atomicAdd(&sAcc[(m + 8) * 49 + n],     acc[i][j][2]);
            atomicAdd(&sAcc[(m + 8) * 49 + n + 1], acc[i][j][3]);
        }
    }
    __syncthreads();
    float* dst = attn + (size_t)(b * HEADS + h) * CH * CH;
    for (int i = tid; i < CH * CH; i += 256)
        atomicAdd(&dst[i], sAcc[(i / CH) * 49 + (i % CH)]);
}

// ---------------- scale + softmax ----------------
__global__ void softmaxk(float* __restrict__ attn, const float* __restrict__ ssq,
                         const float* __restrict__ temp)
{
    int gw = blockIdx.x * (blockDim.x / 32) + (threadIdx.x >> 5);
    if (gw >= B * HEADS * CH) return;
    int lane = threadIdx.x & 31;
    int c = gw % CH, bh = gw / CH, h = bh % HEADS, b = bh / HEADS;
    float* row = attn + (size_t)gw * CH;
    float iq = 1.f / fmaxf(sqrtf(ssq[b * 2 * C + h * CH + c]), EPS);
    float t  = temp[h];
    int e0 = lane, e1 = lane + 32;
    float ik0 = 1.f / fmaxf(sqrtf(ssq[b * 2 * C + C + h * CH + e0]), EPS);
    float x0 = row[e0] * iq * ik0 * t;
    float x1 = -1e30f;
    if (e1 < CH) {
        float ik1 = 1.f / fmaxf(sqrtf(ssq[b * 2 * C + C + h * CH + e1]), EPS);
        x1 = row[e1] * iq * ik1 * t;
    }
    float m = fmaxf(x0, x1);
    #pragma unroll
    for (int o = 16; o > 0; o >>= 1) m = fmaxf(m, __shfl_xor_sync(~0u, m, o));
    float ex0 = expf(x0 - m);
    float ex1 = (e1 < CH) ? expf(x1 - m) : 0.f;
    float s = ex0 + ex1;
    #pragma unroll
    for (int o = 16; o > 0; o >>= 1) s += __shfl_xor_sync(~0u, s, o);
    float r = 1.f / s;
    row[e0] = ex0 * r;
    if (e1 < CH) row[e1] = ex1 * r;
}

// ---------------- fuse proj weights with attention ----------------
__global__ __launch_bounds__(192) void fuseW(const float* __restrict__ proj_w,
                                             const float* __restrict__ attn,
                                             __half* __restrict__ w2)
{
    int bh = blockIdx.x;
    int h = bh % HEADS, b = bh / HEADS;
    __shared__ float At[CH][CH];
    const float* am = attn + (size_t)bh * CH * CH;
    for (int i = threadIdx.x; i < CH * CH; i += 192)
        At[i / CH][i % CH] = am[i];
    __syncthreads();

    int o = threadIdx.x;
    float pr[CH];
    #pragma unroll
    for (int c = 0; c < CH; c++) pr[c] = proj_w[(size_t)o * C + h * CH + c];

    __half* dst = w2 + (size_t)b * C * C + (size_t)o * C + h * CH;
    #pragma unroll 4
    for (int e = 0; e < CH; e++) {
        float acc = 0.f;
        #pragma unroll
        for (int c = 0; c < CH; c++) acc += pr[c] * At[c][e];
        dst[e] = __float2half_rn(acc);
    }
}

// ---------------- launch ----------------
extern "C" void kernel_launch(void* const* d_in, const int* in_sizes, int n_in,
                              void* d_out, int out_size)
{
    const float* x      = (const float*)d_in[0];
    const float* qkv_w  = (const float*)d_in[1];
    const float* qkv_b  = (const float*)d_in[2];
    const float* dw_w   = (const float*)d_in[3];
    const float* dw_b   = (const float*)d_in[4];
    const float* proj_w = (const float*)d_in[5];
    const float* proj_b = (const float*)d_in[6];
    const float* temp   = (const float*)d_in[7];
    float* out = (float*)d_out;

    float *ssqp, *atp;
    __half *xhp, *qkvhp, *dwhp, *whp, *w2p;
    cudaGetSymbolAddress((void**)&xhp,   g_xh);
    cudaGetSymbolAddress((void**)&qkvhp, g_qkvh);
    cudaGetSymbolAddress((void**)&dwhp,  g_dwh);
    cudaGetSymbolAddress((void**)&ssqp,  g_ssq);
    cudaGetSymbolAddress((void**)&atp,   g_at);
    cudaGetSymbolAddress((void**)&whp,   g_wh);
    cudaGetSymbolAddress((void**)&w2p,   g_w2h);

    cudaFuncSetAttribute(qk_mma, cudaFuncAttributeMaxDynamicSharedMemorySize, QK_SMEM);
    cudaFuncSetAttribute(gemm_mma<1>, cudaFuncAttributeMaxDynamicSharedMemorySize, GM_SMEM);
    cudaFuncSetAttribute(gemm_mma<0>, cudaFuncAttributeMaxDynamicSharedMemorySize, GM_SMEM);

    // 1) weights -> fp16 + zero attn
    cvtWz<<<(C3 * C + B * HEADS * CH * CH + 255) / 256, 256>>>(qkv_w, whp, atp);
    // 2) x -> fp16
    cvtX<<<(int)((size_t)B * C * NPTS / 4 / 256), 256>>>(x, xhp);
    // 3) qkv 1x1 conv
    gemm_mma<1><<<dim3(C3 / BMg, NPTS / BNg, B), 512, GM_SMEM>>>(
        xhp, (size_t)C * NPTS, whp, 0, qkv_b, qkvhp, (size_t)C3 * NPTS);
    // 4) depthwise 3x3x3 (fp32x2 packed FMA) <- PROFILED
    dwconv3<<<B * C3, 256>>>(qkvhp, dw_w, dw_b, dwhp, ssqp);
    // 5) q @ k^T
    qk_mma<<<dim3(QK_NSPL, HEADS, B), 256, QK_SMEM>>>(dwhp, atp);
    // 6) scale + softmax
    softmaxk<<<(B * HEADS * CH + 7) / 8, 256>>>(atp, ssqp, temp);
    // 7) fuse proj with attention
    fuseW<<<B * HEADS, 192>>>(proj_w, atp, w2p);
    // 8) fused (proj∘attn) @ v
    gemm_mma<0><<<dim3(1, NPTS / BNg, B), 512, GM_SMEM>>>(
        dwhp + (size_t)2 * C * NPTS, (size_t)C3 * NPTS,
        w2p, (size_t)C * C, proj_b, out, (size_t)C * NPTS);
}

// round 13
// speedup vs baseline: 1.4518x; 1.0753x over previous
#include <cuda_runtime.h>
#include <cuda_fp16.h>
#include <cstdint>

#define B 2
#define C 192
#define C3 576
#define SDIM 32
#define NPTS 32768           // 32^3
#define HEADS 4
#define CH 48
#define EPS 1e-12f

// ---------------- scratch (static device allocations) ----------------
__device__ __half g_xh  [(size_t)B * C * NPTS];      // input x in fp16
__device__ __half g_qkvh[(size_t)B * C3 * NPTS];     // after 1x1 conv (fp16)
__device__ __half g_dwh [(size_t)B * C3 * NPTS];     // after dwconv: q,k,v fp16
__device__ float  g_ssq[B * 2 * C];                  // sum of squares of ROUNDED q/k
__device__ float  g_at [B * HEADS * CH * CH];        // attention logits / probs
__device__ __half g_wh [C3 * C];                     // qkv weights fp16
__device__ __half g_w2h[B * C * C];                  // fused proj∘attn weights fp16

// ================= mma.sync helpers =================
__device__ __forceinline__ uint32_t smem_u32(const void* p) {
    uint32_t a;
    asm("{ .reg .u64 t; cvta.to.shared.u64 t, %1; cvt.u32.u64 %0, t; }" : "=r"(a) : "l"(p));
    return a;
}
__device__ __forceinline__ void ldsm4(uint32_t* r, uint32_t a) {
    asm volatile("ldmatrix.sync.aligned.m8n8.x4.shared.b16 {%0,%1,%2,%3}, [%4];"
                 : "=r"(r[0]), "=r"(r[1]), "=r"(r[2]), "=r"(r[3]) : "r"(a));
}
__device__ __forceinline__ void ldsm4t(uint32_t* r, uint32_t a) {
    asm volatile("ldmatrix.sync.aligned.m8n8.x4.trans.shared.b16 {%0,%1,%2,%3}, [%4];"
                 : "=r"(r[0]), "=r"(r[1]), "=r"(r[2]), "=r"(r[3]) : "r"(a));
}
__device__ __forceinline__ void mma_f16(float* d, const uint32_t* a, const uint32_t* b) {
    asm volatile(
        "mma.sync.aligned.m16n8k16.row.col.f32.f16.f16.f32 "
        "{%0,%1,%2,%3}, {%4,%5,%6,%7}, {%8,%9}, {%0,%1,%2,%3};"
        : "+f"(d[0]), "+f"(d[1]), "+f"(d[2]), "+f"(d[3])
        : "r"(a[0]), "r"(a[1]), "r"(a[2]), "r"(a[3]), "r"(b[0]), "r"(b[1]));
}
#define CP_CG16(dst, src) \
    asm volatile("cp.async.cg.shared.global [%0], [%1], 16;" :: "r"(dst), "l"(src))
#define CP_COMMIT() asm volatile("cp.async.commit_group;")

// ================= packed fp32x2 helpers (sm_100+ family) =================
typedef unsigned long long u64t;
__device__ __forceinline__ u64t pk2(float lo, float hi) {
    u64t d;
    asm("mov.b64 %0, {%1, %2};" : "=l"(d) : "f"(lo), "f"(hi));
    return d;
}
__device__ __forceinline__ void upk2(u64t d, float& lo, float& hi) {
    asm("mov.b64 {%0, %1}, %2;" : "=f"(lo), "=f"(hi) : "l"(d));
}
__device__ __forceinline__ void fma2(u64t& a, u64t x, u64t y) {
    asm("fma.rn.f32x2 %0, %1, %2, %0;" : "+l"(a) : "l"(x), "l"(y));
}
__device__ __forceinline__ u64t add2(u64t x, u64t y) {
    u64t d;
    asm("add.rn.f32x2 %0, %1, %2;" : "=l"(d) : "l"(x), "l"(y));
    return d;
}

// ---------------- setup kernels ----------------
__global__ void cvtWz(const float* __restrict__ qkv_w, __half* __restrict__ wh,
                      float* __restrict__ attn)
{
    int i = blockIdx.x * 256 + threadIdx.x;
    const int T0 = C3 * C;
    const int T1 = T0 + B * HEADS * CH * CH;
    if (i < T0)       wh[i] = __float2half_rn(qkv_w[i]);
    else if (i < T1)  attn[i - T0] = 0.f;
}
__global__ void cvtX(const float* __restrict__ x, __half* __restrict__ xh, size_t base)
{
    size_t i = base + ((size_t)blockIdx.x * 256 + threadIdx.x) * 4;
    float4 v = *reinterpret_cast<const float4*>(&x[i]);
    __half2 h0 = __floats2half2_rn(v.x, v.y);
    __half2 h1 = __floats2half2_rn(v.z, v.w);
    uint2 r = {*reinterpret_cast<uint32_t*>(&h0), *reinterpret_cast<uint32_t*>(&h1)};
    *reinterpret_cast<uint2*>(&xh[i]) = r;
}

// ---------------- 1x1 conv GEMM via fp16 mma.sync, 3-stage cp.async.cg ------------
// 256 threads, BM=96 -> 2 CTAs/SM (independent barrier domains)
#define BMg 96
#define BNg 128
#define BKg 32
#define PA 40
#define PB 136
#define SA_BYTES (BMg * PA * 2)      // 7680
#define SB_BYTES (BKg * PB * 2)      // 8704
#define GM_SMEM  (3 * (SA_BYTES + SB_BYTES))   // 49152
#define NIT (C / BKg)                // 6

template<int OHALF>
__global__ __launch_bounds__(256, 2) void gemm_mma(
    const __half* __restrict__ Xall, size_t xbs,
    const __half* __restrict__ WH, size_t wbs,
    const float* __restrict__ bias, void* __restrict__ Yall, size_t ybs)
{
    extern __shared__ char gsm[];
    const int tid = threadIdx.x, wid = tid >> 5, lane = tid & 31;
    const int o0 = blockIdx.x * BMg;
    const int n0 = blockIdx.y * BNg;
    const __half* X = Xall + (size_t)blockIdx.z * xbs;
    const __half* W = WH + (size_t)blockIdx.z * wbs;

    const int warp_m = (wid >> 2) * 48;   // 2 m-warps x 4 n-warps
    const int warp_n = (wid & 3) * 32;

    const uint32_t bA = smem_u32(gsm);
    const uint32_t bB = bA + 3 * SA_BYTES;
    const uint32_t aOff = ((warp_m + (lane & 15)) * PA + (lane >> 4) * 8) * 2;

    // A: 96x32 halfs = 384 16B-chunks; threads cover rows 0..63, tid<128 rows 64..95
    const int ar0 = tid >> 2,       ac0 = (tid & 3) * 8;
    const int ar1 = 64 + (tid >> 2), ac1 = (tid & 3) * 8;
    // B: 32x128 halfs = 512 chunks; rows 0..15 then 16..31
    const int br0 = tid >> 4,        bc0 = (tid & 15) * 8;
    const int br1 = 16 + (tid >> 4), bc1 = (tid & 15) * 8;

    auto prefetch = [&](int it) {
        const int kc = it * BKg;
        const int s  = it % 3;
        const uint32_t dA = bA + s * SA_BYTES;
        const uint32_t dB = bB + s * SB_BYTES;
        CP_CG16(dA + (ar0 * PA + ac0) * 2, &W[(size_t)(o0 + ar0) * C + kc + ac0]);
        if (tid < 128)
            CP_CG16(dA + (ar1 * PA + ac1) * 2, &W[(size_t)(o0 + ar1) * C + kc + ac1]);
        CP_CG16(dB + (br0 * PB + bc0) * 2, &X[(size_t)(kc + br0) * NPTS + n0 + bc0]);
        CP_CG16(dB + (br1 * PB + bc1) * 2, &X[(size_t)(kc + br1) * NPTS + n0 + bc1]);
        CP_COMMIT();
    };

    prefetch(0);
    prefetch(1);

    float acc[3][4][4] = {};

    #pragma unroll
    for (int it = 0; it < NIT; it++) {
        if (it < NIT - 1) asm volatile("cp.async.wait_group 1;");
        else              asm volatile("cp.async.wait_group 0;");
        __syncthreads();
        if (it + 2 < NIT) prefetch(it + 2);

        const int s = it % 3;
        const uint32_t stA = bA + s * SA_BYTES;
        const uint32_t stB = bB + s * SB_BYTES;
        #pragma unroll
        for (int ks = 0; ks < 2; ks++) {
            uint32_t Bf[4][2];
            #pragma unroll
            for (int jj = 0; jj < 2; jj++) {
                uint32_t r[4];
                uint32_t off = (((lane & 15) + ks * 16) * PB +
                                warp_n + jj * 16 + (lane >> 4) * 8) * 2;
                ldsm4t(r, stB + off);
                Bf[2 * jj][0] = r[0]; Bf[2 * jj][1] = r[1];
                Bf[2 * jj + 1][0] = r[2]; Bf[2 * jj + 1][1] = r[3];
            }
            #pragma unroll
            for (int i = 0; i < 3; i++) {
                uint32_t Af[4];
                ldsm4(Af, stA + aOff + i * (16 * PA * 2) + ks * 32);
                #pragma unroll
                for (int j = 0; j < 4; j++)
                    mma_f16(acc[i][j], Af, Bf[j]);
            }
        }
    }

    #pragma unroll
    for (int i = 0; i < 3; i++) {
        int m = o0 + warp_m + i * 16 + (lane >> 2);
        float bv0 = bias[m], bv1 = bias[m + 8];
        #pragma unroll
        for (int j = 0; j < 4; j++) {
            int n = n0 + warp_n + j * 8 + (lane & 3) * 2;
            if (OHALF) {
                __half* Y = (__half*)Yall + (size_t)blockIdx.z * ybs;
                __half2 r0 = __floats2half2_rn(acc[i][j][0] + bv0, acc[i][j][1] + bv0);
                __half2 r1 = __floats2half2_rn(acc[i][j][2] + bv1, acc[i][j][3] + bv1);
                *reinterpret_cast<__half2*>(&Y[(size_t)m * NPTS + n]) = r0;
                *reinterpret_cast<__half2*>(&Y[(size_t)(m + 8) * NPTS + n]) = r1;
            } else {
                float* Y = (float*)Yall + (size_t)blockIdx.z * ybs;
                float2 r0 = {acc[i][j][0] + bv0, acc[i][j][1] + bv0};
                float2 r1 = {acc[i][j][2] + bv1, acc[i][j][3] + bv1};
                *reinterpret_cast<float2*>(&Y[(size_t)m * NPTS + n]) = r0;
                *reinterpret_cast<float2*>(&Y[(size_t)(m + 8) * NPTS + n]) = r1;
            }
        }
    }
}

// ---------------- depthwise 3x3x3: z-rotation + packed fp32x2 FMA ------------------
__global__ __launch_bounds__(256) void dwconv3(
    const __half* __restrict__ in, const float* __restrict__ w,
    const float* __restrict__ bias, __half* __restrict__ outh,
    float* __restrict__ ssq)
{
    int bc = blockIdx.x;
    int b  = bc / C3;
    int c  = bc % C3;
    const __half* vol = in + (size_t)bc * NPTS;
    __half* op = outh + (size_t)bc * NPTS;

    u64t ww[27];                         // packed (w,w) pairs
    #pragma unroll
    for (int i = 0; i < 27; i++) { float wv = w[c * 27 + i]; ww[i] = pk2(wv, wv); }
    float bv = bias[c];
    const u64t bb = pk2(bv, bv);

    __shared__ float P[2][34][36];
    __shared__ float sred[8];
    int tid = threadIdx.x;
    for (int i = tid; i < 2 * 34 * 36; i += 256) ((float*)P)[i] = 0.f;
    __syncthreads();

    const int ly = tid >> 3, lx4 = (tid & 7) * 4;
    {   // plane 0 -> slot 0
        uint2 raw = *reinterpret_cast<const uint2*>(&vol[ly * 32 + lx4]);
        __half2 hA = *reinterpret_cast<__half2*>(&raw.x);
        __half2 hB = *reinterpret_cast<__half2*>(&raw.y);
        P[0][1 + ly][1 + lx4 + 0] = __half2float(hA.x);
        P[0][1 + ly][1 + lx4 + 1] = __half2float(hA.y);
        P[0][1 + ly][1 + lx4 + 2] = __half2float(hB.x);
        P[0][1 + ly][1 + lx4 + 3] = __half2float(hB.y);
    }
    __syncthreads();

    float qs = 0.f;
    const bool is_qk = (c < 2 * C);

    u64t a0L = bb, a0H = bb, a1L = bb, a1H = bb;   // carried out[z], out[z+1]

    for (int z = 0; z < SDIM; z++) {
        uint2 raw;
        if (z + 1 < SDIM)
            raw = *reinterpret_cast<const uint2*>(&vol[(size_t)(z + 1) * 1024 + ly * 32 + lx4]);

        u64t cdL[3] = {0, 0, 0}, cdH[3] = {0, 0, 0};
        const int s = z & 1;
        #pragma unroll
        for (int dy = 0; dy < 3; dy++) {
            const float* row = &P[s][ly + dy][lx4];
            float4 rA = *reinterpret_cast<const float4*>(row);
            float2 rB = *reinterpret_cast<const float2*>(row + 4);
            u64t p0 = pk2(rA.x, rA.y), p1 = pk2(rA.y, rA.z), p2 = pk2(rA.z, rA.w);
            u64t p3 = pk2(rA.w, rB.x), p4 = pk2(rB.x, rB.y);
            #pragma unroll
            for (int dz = 0; dz < 3; dz++) {
                const int base = dz * 9 + dy * 3;
                fma2(cdL[dz], ww[base + 0], p0);
                fma2(cdL[dz], ww[base + 1], p1);
                fma2(cdL[dz], ww[base + 2], p2);
                fma2(cdH[dz], ww[base + 0], p2);
                fma2(cdH[dz], ww[base + 1], p3);
                fma2(cdH[dz], ww[base + 2], p4);
            }
        }

        if (z > 0) {
            u64t oL = add2(a0L, cdL[2]);
            u64t oH = add2(a0H, cdH[2]);
            float o0, o1, o2, o3;
            upk2(oL, o0, o1); upk2(oH, o2, o3);
            __half2 h0 = __floats2half2_rn(o0, o1);
            __half2 h1 = __floats2half2_rn(o2, o3);
            uint2 hv = {*reinterpret_cast<uint32_t*>(&h0), *reinterpret_cast<uint32_t*>(&h1)};
            *reinterpret_cast<uint2*>(&op[(size_t)(z - 1) * 1024 + ly * 32 + lx4]) = hv;
            if (is_qk) {
                float r0 = __half2float(h0.x), r1 = __half2float(h0.y);
                float r2 = __half2float(h1.x), r3 = __half2float(h1.y);
                qs += r0 * r0 + r1 * r1 + r2 * r2 + r3 * r3;
            }
        }
        a0L = add2(a1L, cdL[1]); a0H = add2(a1H, cdH[1]);
        a1L = add2(bb, cdL[0]);  a1H = add2(bb, cdH[0]);

        if (z + 1 < SDIM) {
            __half2 hA = *reinterpret_cast<__half2*>(&raw.x);
            __half2 hB = *reinterpret_cast<__half2*>(&raw.y);
            P[s ^ 1][1 + ly][1 + lx4 + 0] = __half2float(hA.x);
            P[s ^ 1][1 + ly][1 + lx4 + 1] = __half2float(hA.y);
            P[s ^ 1][1 + ly][1 + lx4 + 2] = __half2float(hB.x);
            P[s ^ 1][1 + ly][1 + lx4 + 3] = __half2float(hB.y);
        }
        __syncthreads();
    }
    {   // out[31]
        float o0, o1, o2, o3;
        upk2(a0L, o0, o1); upk2(a0H, o2, o3);
        __half2 h0 = __floats2half2_rn(o0, o1);
        __half2 h1 = __floats2half2_rn(o2, o3);
        uint2 hv = {*reinterpret_cast<uint32_t*>(&h0), *reinterpret_cast<uint32_t*>(&h1)};
        *reinterpret_cast<uint2*>(&op[(size_t)31 * 1024 + ly * 32 + lx4]) = hv;
        if (is_qk) {
            float r0 = __half2float(h0.x), r1 = __half2float(h0.y);
            float r2 = __half2float(h1.x), r3 = __half2float(h1.y);
            qs += r0 * r0 + r1 * r1 + r2 * r2 + r3 * r3;
        }
    }

    if (is_qk) {
        #pragma unroll
        for (int o = 16; o > 0; o >>= 1) qs += __shfl_xor_sync(~0u, qs, o);
        if ((tid & 31) == 0) sred[tid >> 5] = qs;
        __syncthreads();
        if (tid < 8) {
            float v = sred[tid];
            #pragma unroll
            for (int o = 4; o > 0; o >>= 1) v += __shfl_xor_sync(0xffu, v, o);
            if (tid == 0) ssq[b * 2 * C + c] = v;
        }
    }
}

// ---------------- q @ k^T via fp16 mma.sync ----------------
#define QKC 128
#define QKP 136
#define QK_ARR (48 * QKP * 2)
#define QK_STAGE (2 * QK_ARR)
#define QK_NSPL 32
#define QK_SLAB (NPTS / QK_NSPL)     // 1024
#define QK_SMEM (2 * QK_STAGE + 48 * 49 * 4)

__global__ __launch_bounds__(256) void qk_mma(
    const __half* __restrict__ dwh, float* __restrict__ attn)
{
    extern __shared__ char smem[];
    float* sAcc = reinterpret_cast<float*>(smem + 2 * QK_STAGE);
    const int tid = threadIdx.x, wid = tid >> 5, lane = tid & 31;
    const int b = blockIdx.z, h = blockIdx.y;
    const int n0 = blockIdx.x * QK_SLAB;

    const __half* srcs[2] = {
        dwh + ((size_t)b * C3 + h * CH) * NPTS,
        dwh + ((size_t)b * C3 + C + h * CH) * NPTS
    };
    const uint32_t sbase = smem_u32(smem);

    for (int i = tid; i < 48 * 49; i += 256) sAcc[i] = 0.f;

    int la[6], lr[6], lc[6];
    #pragma unroll
    for (int q = 0; q < 6; q++) {
        int idx = tid + q * 256;
        la[q] = idx / 768;
        int rem = idx % 768;
        lr[q] = rem / 16;
        lc[q] = (rem % 16) * 8;
    }

    const int NCH = QK_SLAB / QKC;
    #pragma unroll
    for (int q = 0; q < 6; q++) {
        uint32_t dst = sbase + la[q] * QK_ARR + (lr[q] * QKP + lc[q]) * 2;
        CP_CG16(dst, srcs[la[q]] + (size_t)lr[q] * NPTS + n0 + lc[q]);
    }
    CP_COMMIT();

    float acc[3][6][4] = {};
    const int k0 = wid * 16;

    for (int ch = 0; ch < NCH; ch++) {
        if (ch + 1 < NCH) {
            uint32_t st = ((ch + 1) & 1) * QK_STAGE;
            int nb = n0 + (ch + 1) * QKC;
            #pragma unroll
            for (int q = 0; q < 6; q++) {
                uint32_t dst = sbase + st + la[q] * QK_ARR + (lr[q] * QKP + lc[q]) * 2;
                CP_CG16(dst, srcs[la[q]] + (size_t)lr[q] * NPTS + nb + lc[q]);
            }
            CP_COMMIT();
            asm volatile("cp.async.wait_group 1;");
        } else {
            asm volatile("cp.async.wait_group 0;");
        }
        __syncthreads();

        const uint32_t st = sbase + (ch & 1) * QK_STAGE;
        uint32_t Af[3][4], Bf[6][2];
        #pragma unroll
        for (int i = 0; i < 3; i++) {
            uint32_t off = ((i * 16 + (lane & 15)) * QKP + k0 + (lane >> 4) * 8) * 2;
            ldsm4(Af[i], st + off);
        }
        #pragma unroll
        for (int jj = 0; jj < 3; jj++) {
            uint32_t r[4];
            uint32_t off = ((jj * 16 + (lane & 7) + ((lane >> 4) << 3)) * QKP +
                            k0 + ((lane >> 3) & 1) * 8) * 2;
            ldsm4(r, st + QK_ARR + off);
            Bf[2 * jj][0] = r[0]; Bf[2 * jj][1] = r[1];
            Bf[2 * jj + 1][0] = r[2]; Bf[2 * jj + 1][1] = r[3];
        }
        #pragma unroll
        for (int i = 0; i < 3; i++)
            #pragma unroll
            for (int j = 0; j < 6; j++)
                mma_f16(acc[i][j], Af[i], Bf[j]);
        __syncthreads();
    }

    #pragma unroll
    for (int i = 0; i < 3; i++) {
        int m = i * 16 + (lane >> 2);
        #pragma unroll
        for (int j = 0; j < 6; j++) {
            int n = j * 8 + (lane & 3) * 2;
            atomicAdd(&sAcc[m * 49 + n],           acc[i][j][0]);
            atomicAdd(&sAcc[m * 49 + n + 1],       acc[i][j][1]);
            atomicAdd(&sAcc[(m + 8) * 49 + n],     acc[i][j][2]);
            atomicAdd(&sAcc[(m + 8) * 49 + n + 1], acc[i][j][3]);
        }
    }
    __syncthreads();
    float* dst = attn + (size_t)(b * HEADS + h) * CH * CH;
    for (int i = tid; i < CH * CH; i += 256)
        atomicAdd(&dst[i], sAcc[(i / CH) * 49 + (i % CH)]);
}

// ---------------- scale + softmax ----------------
__global__ void softmaxk(float* __restrict__ attn, const float* __restrict__ ssq,
                         const float* __restrict__ temp)
{
    int gw = blockIdx.x * (blockDim.x / 32) + (threadIdx.x >> 5);
    if (gw >= B * HEADS * CH) return;
    int lane = threadIdx.x & 31;
    int c = gw % CH, bh = gw / CH, h = bh % HEADS, b = bh / HEADS;
    float* row = attn + (size_t)gw * CH;
    float iq = 1.f / fmaxf(sqrtf(ssq[b * 2 * C + h * CH + c]), EPS);
    float t  = temp[h];
    int e0 = lane, e1 = lane + 32;
    float ik0 = 1.f / fmaxf(sqrtf(ssq[b * 2 * C + C + h * CH + e0]), EPS);
    float x0 = row[e0] * iq * ik0 * t;
    float x1 = -1e30f;
    if (e1 < CH) {
        float ik1 = 1.f / fmaxf(sqrtf(ssq[b * 2 * C + C + h * CH + e1]), EPS);
        x1 = row[e1] * iq * ik1 * t;
    }
    float m = fmaxf(x0, x1);
    #pragma unroll
    for (int o = 16; o > 0; o >>= 1) m = fmaxf(m, __shfl_xor_sync(~0u, m, o));
    float ex0 = expf(x0 - m);
    float ex1 = (e1 < CH) ? expf(x1 - m) : 0.f;
    float s = ex0 + ex1;
    #pragma unroll
    for (int o = 16; o > 0; o >>= 1) s += __shfl_xor_sync(~0u, s, o);
    float r = 1.f / s;
    row[e0] = ex0 * r;
    if (e1 < CH) row[e1] = ex1 * r;
}

// ---------------- fuse proj weights with attention ----------------
__global__ __launch_bounds__(192) void fuseW(const float* __restrict__ proj_w,
                                             const float* __restrict__ attn,
                                             __half* __restrict__ w2)
{
    int bh = blockIdx.x;
    int h = bh % HEADS, b = bh / HEADS;
    __shared__ float At[CH][CH];
    const float* am = attn + (size_t)bh * CH * CH;
    for (int i = threadIdx.x; i < CH * CH; i += 192)
        At[i / CH][i % CH] = am[i];
    __syncthreads();

    int o = threadIdx.x;
    float pr[CH];
    #pragma unroll
    for (int c = 0; c < CH; c++) pr[c] = proj_w[(size_t)o * C + h * CH + c];

    __half* dst = w2 + (size_t)b * C * C + (size_t)o * C + h * CH;
    #pragma unroll 4
    for (int e = 0; e < CH; e++) {
        float acc = 0.f;
        #pragma unroll
        for (int c = 0; c < CH; c++) acc += pr[c] * At[c][e];
        dst[e] = __float2half_rn(acc);
    }
}

// ---------------- launch ----------------
extern "C" void kernel_launch(void* const* d_in, const int* in_sizes, int n_in,
                              void* d_out, int out_size)
{
    const float* x      = (const float*)d_in[0];
    const float* qkv_w  = (const float*)d_in[1];
    const float* qkv_b  = (const float*)d_in[2];
    const float* dw_w   = (const float*)d_in[3];
    const float* dw_b   = (const float*)d_in[4];
    const float* proj_w = (const float*)d_in[5];
    const float* proj_b = (const float*)d_in[6];
    const float* temp   = (const float*)d_in[7];
    float* out = (float*)d_out;

    float *ssqp, *atp;
    __half *xhp, *qkvhp, *dwhp, *whp, *w2p;
    cudaGetSymbolAddress((void**)&xhp,   g_xh);
    cudaGetSymbolAddress((void**)&qkvhp, g_qkvh);
    cudaGetSymbolAddress((void**)&dwhp,  g_dwh);
    cudaGetSymbolAddress((void**)&ssqp,  g_ssq);
    cudaGetSymbolAddress((void**)&atp,   g_at);
    cudaGetSymbolAddress((void**)&whp,   g_wh);
    cudaGetSymbolAddress((void**)&w2p,   g_w2h);

    cudaFuncSetAttribute(qk_mma, cudaFuncAttributeMaxDynamicSharedMemorySize, QK_SMEM);
    cudaFuncSetAttribute(gemm_mma<1>, cudaFuncAttributeMaxDynamicSharedMemorySize, GM_SMEM);
    cudaFuncSetAttribute(gemm_mma<0>, cudaFuncAttributeMaxDynamicSharedMemorySize, GM_SMEM);

    const size_t XTOT = (size_t)B * C * NPTS;
    // 1) weights -> fp16 + zero attn
    cvtWz<<<(C3 * C + B * HEADS * CH * CH + 255) / 256, 256>>>(qkv_w, whp, atp);
    // 2-3) x -> fp16 in two halves (keeps new gemm at profiled slot #4)
    cvtX<<<(int)(XTOT / 2 / 4 / 256), 256>>>(x, xhp, 0);
    cvtX<<<(int)(XTOT / 2 / 4 / 256), 256>>>(x, xhp, XTOT / 2);
    // 4) qkv 1x1 conv (256-thread, 2 CTAs/SM) <- PROFILED
    gemm_mma<1><<<dim3(C3 / BMg, NPTS / BNg, B), 256, GM_SMEM>>>(
        xhp, (size_t)C * NPTS, whp, 0, qkv_b, qkvhp, (size_t)C3 * NPTS);
    // 5) depthwise 3x3x3
    dwconv3<<<B * C3, 256>>>(qkvhp, dw_w, dw_b, dwhp, ssqp);
    // 6) q @ k^T
    qk_mma<<<dim3(QK_NSPL, HEADS, B), 256, QK_SMEM>>>(dwhp, atp);
    // 7) scale + softmax
    softmaxk<<<(B * HEADS * CH + 7) / 8, 256>>>(atp, ssqp, temp);
    // 8) fuse proj with attention
    fuseW<<<B * HEADS, 192>>>(proj_w, atp, w2p);
    // 9) fused (proj∘attn) @ v
    gemm_mma<0><<<dim3(C / BMg, NPTS / BNg, B), 256, GM_SMEM>>>(
        dwhp + (size_t)2 * C * NPTS, (size_t)C3 * NPTS,
        w2p, (size_t)C * C, proj_b, out, (size_t)C * NPTS);
}